// round 14
// baseline (speedup 1.0000x reference)
#include <cuda_runtime.h>
#include <cuda_fp16.h>
#include <math.h>
#include <stdint.h>

#define BATCH 8
#define SEQ   2048
#define DIM   512
#define NCHUNK 8          // 256-row chunks of SEQ (dots M-tiles)
#define NR    (BATCH * SEQ)
#define LN_BLOCKS (NR)            // 2*NR rows, 2 rows per block
#define TS_BLOCKS 768             // 3 weights x 256 tiles

static const float LN_EPS_F = 1e-5f;

// ---------------- scratch (static device globals; no allocation) ----------------
__device__ __align__(256) __half g_xc [(size_t)2 * NR * DIM];   // [xn | cn]
__device__ __align__(256) __half g_wqk[(size_t)2 * DIM * DIM];  // [Wq^T | Wk^T]
__device__ __align__(256) __half g_wvt[(size_t)DIM * DIM];
__device__ __align__(256) __half g_qk [(size_t)2 * NR * DIM];   // [q | k]
__device__ __align__(256) __half g_vt [(size_t)BATCH * DIM * SEQ];  // vt' = vt * csi
__device__ __align__(256) __half g_e  [(size_t)BATCH * SEQ * SEQ];  // E = exp(dots*scale)
__device__ float g_ps  [BATCH * NCHUNK * SEQ];
__device__ float g_csi [BATCH * SEQ];
__device__ float g_rinv[BATCH * SEQ];
__device__ float g_bqk [2 * DIM];

// ---------------- PTX helpers (baseline compute_103-safe) ----------------
__device__ __forceinline__ uint32_t smem_u32(const void* p) {
    uint32_t a;
    asm("{ .reg .u64 t; cvta.to.shared.u64 t, %1; cvt.u32.u64 %0, t; }" : "=r"(a) : "l"(p));
    return a;
}
__device__ __forceinline__ void cp_async16(uint32_t d, const void* g) {
    asm volatile("cp.async.cg.shared.global [%0], [%1], 16;" :: "r"(d), "l"(g));
}
__device__ __forceinline__ void cp_commit() {
    asm volatile("cp.async.commit_group;" ::: "memory");
}
template <int N>
__device__ __forceinline__ void cp_wait() {
    asm volatile("cp.async.wait_group %0;" :: "n"(N) : "memory");
}
__device__ __forceinline__ void ldsm4(uint32_t& r0, uint32_t& r1, uint32_t& r2, uint32_t& r3,
                                      uint32_t addr) {
    asm volatile("ldmatrix.sync.aligned.m8n8.x4.shared.b16 {%0,%1,%2,%3}, [%4];"
                 : "=r"(r0), "=r"(r1), "=r"(r2), "=r"(r3) : "r"(addr));
}
__device__ __forceinline__ void mma16816(float* c, const uint32_t* a, uint32_t b0, uint32_t b1) {
    asm volatile(
        "mma.sync.aligned.m16n8k16.row.col.f32.f16.f16.f32 "
        "{%0,%1,%2,%3}, {%4,%5,%6,%7}, {%8,%9}, {%0,%1,%2,%3};"
        : "+f"(c[0]), "+f"(c[1]), "+f"(c[2]), "+f"(c[3])
        : "r"(a[0]), "r"(a[1]), "r"(a[2]), "r"(a[3]), "r"(b0), "r"(b1));
}

// ---------------- HMMA plain-fp16 GEMM, CTA tile 256x128, warp tile 64x64 ----
// BK=64 per stage (4 k-steps of 16), 4 smem stages.
// C[M,N] = A[M,Kc] @ B[N,Kc]^T  (A,B fp16 K-major); M%256==0, N%128==0, Kc%64==0
// pattern 0: outf = (acc*alpha + bias_col + bias_row) * rowscale[z*M+row]
// pattern 5: outh = fp16((acc*alpha + bias_col + bias_row) * colscale)
// pattern 6: outh = fp16(exp(acc*alpha)); fused column sums -> g_ps (per 256-row chunk)
// bias_col[z*bias_zs + col]; colscale[z*cs_zs + col]
#define BK 64
#define STAGES 4
#define PITCH 144                      // 128B data + 16B pad per row
#define A_STAGE (256 * PITCH)
#define B_STAGE (128 * PITCH)
#define STAGE_BYTES (A_STAGE + B_STAGE)
#define GEMM_DSMEM (STAGES * STAGE_BYTES)   // 221184 bytes

__global__ void __launch_bounds__(256, 1) gemm_h(
    const __half* __restrict__ A, const __half* __restrict__ B,
    int M, int N, int Kc,
    size_t sA, size_t sB, size_t sC,
    float alpha,
    const float* __restrict__ bias_col, int bias_zs,
    const float* __restrict__ bias_row,
    const float* __restrict__ rowscale,
    const float* __restrict__ colscale, int cs_zs,
    float* __restrict__ outf, __half* __restrict__ outh, int pattern)
{
    extern __shared__ char dyn[];
    uint32_t dynb = smem_u32(dyn);

    int z = blockIdx.z;
    const __half* Ab = A + (size_t)z * sA + (size_t)(blockIdx.y * 256) * Kc;
    const __half* Bb = B + (size_t)z * sB + (size_t)(blockIdx.x * 128) * Kc;
    int bm = blockIdx.y * 256;
    int bn = blockIdx.x * 128;

    int t = threadIdx.x;
    int wid = t >> 5, lane = t & 31;
    int wm = wid & 3;        // 4 warps over M (64 rows each)
    int wn = wid >> 2;       // 2 warps over N (64 cols each)

    float acc[4][8][4];
    #pragma unroll
    for (int i = 0; i < 4; i++)
        #pragma unroll
        for (int j = 0; j < 8; j++)
            #pragma unroll
            for (int r = 0; r < 4; r++) acc[i][j][r] = 0.0f;

    int nkb = Kc / BK;

    auto issue = [&](int kb) {
        int slot = kb % STAGES;
        uint32_t sa = dynb + slot * STAGE_BYTES;
        uint32_t sb = sa + A_STAGE;
        int kh = kb * BK;
        #pragma unroll
        for (int i = 0; i < 8; i++) {           // A: 256 rows x 64 k (8 chunks/row)
            int idx = t + 256 * i;
            int row = idx >> 3, c = idx & 7;
            cp_async16(sa + row * PITCH + c * 16, Ab + (size_t)row * Kc + kh + c * 8);
        }
        #pragma unroll
        for (int i = 0; i < 4; i++) {           // B: 128 rows x 64 k
            int idx = t + 256 * i;
            int row = idx >> 3, c = idx & 7;
            cp_async16(sb + row * PITCH + c * 16, Bb + (size_t)row * Kc + kh + c * 8);
        }
    };

    issue(0); cp_commit();
    issue(1); cp_commit();
    issue(2); cp_commit();

    uint32_t a_lane = (uint32_t)((wm * 64 + (lane & 15)) * PITCH + ((lane >> 4) * 8) * 2);
    uint32_t b_lane = (uint32_t)(A_STAGE +
                       (wn * 64 + (lane & 7) + (lane >> 4) * 8) * PITCH +
                       (((lane >> 3) & 1) * 8) * 2);

    cp_wait<1>();          // groups 0,1 done -> slots 0,1 ready
    __syncthreads();

    uint32_t af[2][4][4];  // A fragments, double buffered (4 x m16)
    uint32_t bf[2][4][4];  // B fragments, double buffered (4 x n16)

    {
        uint32_t s0 = dynb;
        #pragma unroll
        for (int mi = 0; mi < 4; mi++)
            ldsm4(af[0][mi][0], af[0][mi][1], af[0][mi][2], af[0][mi][3],
                  s0 + a_lane + mi * (16 * PITCH));
        #pragma unroll
        for (int g = 0; g < 4; g++)
            ldsm4(bf[0][g][0], bf[0][g][1], bf[0][g][2], bf[0][g][3],
                  s0 + b_lane + g * (16 * PITCH));
    }

    int p = 0;
    for (int kb = 0; kb < nkb; kb++) {
        if (kb + 3 < nkb) issue(kb + 3);
        cp_commit();
        uint32_t scur = dynb + (kb % STAGES) * STAGE_BYTES;
        uint32_t snxt = dynb + ((kb + 1) % STAGES) * STAGE_BYTES;

        #pragma unroll
        for (int ks = 0; ks < 4; ks++) {
            // prefetch fragments for next k-step (or next stage's ks=0)
            bool last = (kb + 1 >= nkb) && (ks == 3);
            if (!last) {
                uint32_t src = (ks < 3) ? (scur + (ks + 1) * 32) : snxt;
                #pragma unroll
                for (int mi = 0; mi < 4; mi++)
                    ldsm4(af[p^1][mi][0], af[p^1][mi][1], af[p^1][mi][2], af[p^1][mi][3],
                          src + a_lane + mi * (16 * PITCH));
                #pragma unroll
                for (int g = 0; g < 4; g++)
                    ldsm4(bf[p^1][g][0], bf[p^1][g][1], bf[p^1][g][2], bf[p^1][g][3],
                          src + b_lane + g * (16 * PITCH));
            }
            #pragma unroll
            for (int mi = 0; mi < 4; mi++)
                #pragma unroll
                for (int ni = 0; ni < 8; ni++)
                    mma16816(acc[mi][ni], af[p][mi],
                             bf[p][ni >> 1][(ni & 1) * 2], bf[p][ni >> 1][(ni & 1) * 2 + 1]);
            p ^= 1;
        }

        cp_wait<1>();
        __syncthreads();
    }

    // ---------------- store epilogue ----------------
    int r_lane = lane >> 2;
    int c_lane = (lane & 3) * 2;

    if (pattern == 6) {
        float csum[8][2];
        #pragma unroll
        for (int ni = 0; ni < 8; ni++) { csum[ni][0] = 0.0f; csum[ni][1] = 0.0f; }

        #pragma unroll
        for (int mi = 0; mi < 4; mi++) {
            #pragma unroll
            for (int ni = 0; ni < 8; ni++) {
                int row = bm + wm * 64 + mi * 16 + r_lane;
                int col = bn + wn * 64 + ni * 8 + c_lane;
                float* a4 = acc[mi][ni];
                #pragma unroll
                for (int h = 0; h < 2; h++) {
                    int rr = row + h * 8;
                    float e0 = __expf(a4[h * 2 + 0] * alpha);
                    float e1 = __expf(a4[h * 2 + 1] * alpha);
                    csum[ni][0] += e0;
                    csum[ni][1] += e1;
                    __half2 hh = __halves2half2(__float2half_rn(e0), __float2half_rn(e1));
                    *(__half2*)(outh + (size_t)z * sC + (size_t)rr * N + col) = hh;
                }
            }
        }
        // reduce over the 8 lane-rows (lane bits 2..4)
        #pragma unroll
        for (int o = 4; o < 32; o <<= 1)
            #pragma unroll
            for (int ni = 0; ni < 8; ni++) {
                csum[ni][0] += __shfl_xor_sync(0xffffffffu, csum[ni][0], o);
                csum[ni][1] += __shfl_xor_sync(0xffffffffu, csum[ni][1], o);
            }
        cp_wait<0>();
        __syncthreads();
        float* ssm = (float*)dyn;            // [4][128]
        if ((lane >> 2) == 0) {
            #pragma unroll
            for (int ni = 0; ni < 8; ni++) {
                int col = wn * 64 + ni * 8 + (lane & 3) * 2;
                ssm[wm * 128 + col]     = csum[ni][0];
                ssm[wm * 128 + col + 1] = csum[ni][1];
            }
        }
        __syncthreads();
        if (t < 128) {
            float s = ssm[t] + ssm[128 + t] + ssm[256 + t] + ssm[384 + t];
            g_ps[((size_t)z * NCHUNK + blockIdx.y) * SEQ + bn + t] = s;
        }
        return;
    }

    #pragma unroll
    for (int mi = 0; mi < 4; mi++) {
        #pragma unroll
        for (int ni = 0; ni < 8; ni++) {
            int row = bm + wm * 64 + mi * 16 + r_lane;
            int col = bn + wn * 64 + ni * 8 + c_lane;
            float* a4 = acc[mi][ni];
            float bc0 = bias_col ? bias_col[z * bias_zs + col]     : 0.0f;
            float bc1 = bias_col ? bias_col[z * bias_zs + col + 1] : 0.0f;
            float cs0 = colscale ? colscale[z * cs_zs + col]       : 1.0f;
            float cs1 = colscale ? colscale[z * cs_zs + col + 1]   : 1.0f;
            #pragma unroll
            for (int h = 0; h < 2; h++) {
                int rr = row + h * 8;
                float br = bias_row ? bias_row[rr] : 0.0f;
                float v0 = (a4[h * 2 + 0] * alpha + bc0 + br) * cs0;
                float v1 = (a4[h * 2 + 1] * alpha + bc1 + br) * cs1;
                if (pattern == 0) {
                    float rs = rowscale ? rowscale[(size_t)z * M + rr] : 1.0f;
                    float2 o = make_float2(v0 * rs, v1 * rs);
                    *(float2*)(outf + (size_t)z * sC + (size_t)rr * N + col) = o;
                } else {  // pattern 5: plain fp16
                    __half2 hh = __halves2half2(__float2half_rn(v0), __float2half_rn(v1));
                    *(__half2*)(outh + (size_t)z * sC + (size_t)rr * N + col) = hh;
                }
            }
        }
    }
}

// ---------------- unified prep: LN (2 rows/block) + 3 weight transposes + bias pack ----
__global__ void __launch_bounds__(256) prep_kernel(
    const float* __restrict__ xin, const float* __restrict__ cin,
    const float* __restrict__ gx, const float* __restrict__ bx,
    const float* __restrict__ gc, const float* __restrict__ bc,
    const float* __restrict__ Wq, const float* __restrict__ Wk,
    const float* __restrict__ Wv,
    const float* __restrict__ bq, const float* __restrict__ bk)
{
    int blk = blockIdx.x;
    if (blk < LN_BLOCKS) {
        // two LN rows per block: rows 2*blk, 2*blk+1 of combined [x | c]
        __shared__ float sh[2][8];
        int half = threadIdx.x >> 7;      // 0 or 1
        int t = threadIdx.x & 127;
        int row = blk * 2 + half;         // 0 .. 2*NR-1
        const float* x;
        const float* g;
        const float* b;
        __half* y;
        if (row < NR) {
            x = xin + (size_t)row * DIM; g = gx; b = bx;
            y = g_xc + (size_t)row * DIM;
        } else {
            int r2 = row - NR;
            x = cin + (size_t)r2 * DIM; g = gc; b = bc;
            y = g_xc + (size_t)NR * DIM + (size_t)r2 * DIM;
        }
        float4 v = ((const float4*)x)[t];
        float s  = v.x + v.y + v.z + v.w;
        float ss = v.x*v.x + v.y*v.y + v.z*v.z + v.w*v.w;
        #pragma unroll
        for (int o = 16; o > 0; o >>= 1) {
            s  += __shfl_down_sync(0xffffffffu, s, o);
            ss += __shfl_down_sync(0xffffffffu, ss, o);
        }
        if ((t & 31) == 0) { sh[half][t >> 5] = s; sh[half][4 + (t >> 5)] = ss; }
        __syncthreads();
        float fs  = sh[half][0] + sh[half][1] + sh[half][2] + sh[half][3];
        float fss = sh[half][4] + sh[half][5] + sh[half][6] + sh[half][7];
        float mu  = fs * (1.0f / DIM);
        float var = fss * (1.0f / DIM) - mu * mu;
        float rstd = rsqrtf(var + LN_EPS_F);
        float4 gv = ((const float4*)g)[t];
        float4 bv = ((const float4*)b)[t];
        float o0 = (v.x - mu) * rstd * gv.x + bv.x;
        float o1 = (v.y - mu) * rstd * gv.y + bv.y;
        float o2 = (v.z - mu) * rstd * gv.z + bv.z;
        float o3 = (v.w - mu) * rstd * gv.w + bv.w;
        ((__half2*)(y + t * 4))[0] = __halves2half2(__float2half_rn(o0), __float2half_rn(o1));
        ((__half2*)(y + t * 4))[1] = __halves2half2(__float2half_rn(o2), __float2half_rn(o3));
    } else if (blk < LN_BLOCKS + TS_BLOCKS) {
        // weight transpose tiles
        __shared__ float tile[32][33];
        int idx = blk - LN_BLOCKS;
        int which = idx >> 8;      // 0..2
        int tl = idx & 255;        // 16x16 tiles
        const float* in = (which == 0) ? Wq : (which == 1) ? Wk : Wv;
        __half* out = (which == 0) ? g_wqk
                    : (which == 1) ? (g_wqk + (size_t)DIM * DIM) : g_wvt;
        int r0 = (tl >> 4) * 32, c0 = (tl & 15) * 32;
        int tx = threadIdx.x & 31, ty = threadIdx.x >> 5;
        #pragma unroll
        for (int i = ty; i < 32; i += 8)
            tile[i][tx] = in[(size_t)(r0 + i) * DIM + c0 + tx];
        __syncthreads();
        #pragma unroll
        for (int i = ty; i < 32; i += 8)
            out[(size_t)(c0 + i) * DIM + r0 + tx] = __float2half_rn(tile[tx][i]);
    } else {
        // bias pack
        for (int t = threadIdx.x; t < DIM; t += 256) {
            g_bqk[t] = bq[t];
            g_bqk[DIM + t] = bk[t];
        }
    }
}

// ---------------- column sums combine -> 1/colsum ----------------
__global__ void __launch_bounds__(256) colstats2_kernel() {
    int j = blockIdx.x * 256 + threadIdx.x;
    int z = blockIdx.y;
    float s = 0.0f;
    #pragma unroll
    for (int c = 0; c < NCHUNK; c++)
        s += g_ps[((size_t)z * NCHUNK + c) * SEQ + j];
    g_csi[(size_t)z * SEQ + j] = 1.0f / s;
}

// ---------------- rowsum: rinv[i] = 1 / sum_j E[i,j]*csi[j] (read-only over E) ----
__global__ void __launch_bounds__(256) rowsum_kernel() {
    int i = blockIdx.x;
    int z = blockIdx.y;
    int t = threadIdx.x;
    const __half* row = g_e + ((size_t)z * SEQ + i) * SEQ;
    const float* ci = g_csi + (size_t)z * SEQ;
    float acc = 0.0f;
    #pragma unroll
    for (int j2 = t; j2 < SEQ / 2; j2 += 256) {
        int j = j2 * 2;
        __half2 e2 = *(const __half2*)(row + j);
        float2 c2 = *(const float2*)(ci + j);
        acc += __half2float(__low2half(e2))  * c2.x
             + __half2float(__high2half(e2)) * c2.y;
    }
    __shared__ float sh[8];
    #pragma unroll
    for (int o = 16; o > 0; o >>= 1)
        acc += __shfl_down_sync(0xffffffffu, acc, o);
    if ((t & 31) == 0) sh[t >> 5] = acc;
    __syncthreads();
    if (t == 0) {
        float s = 0.0f;
        #pragma unroll
        for (int w = 0; w < 8; w++) s += sh[w];
        g_rinv[(size_t)z * SEQ + i] = 1.0f / s;
    }
}

// ---------------- launch ----------------
extern "C" void kernel_launch(void* const* d_in, const int* in_sizes, int n_in,
                              void* d_out, int out_size) {
    const float* inputs  = (const float*)d_in[0];
    const float* context = (const float*)d_in[1];
    const float* gin  = (const float*)d_in[2];
    const float* bin  = (const float*)d_in[3];
    const float* gctx = (const float*)d_in[4];
    const float* bctx = (const float*)d_in[5];
    const float* Wq = (const float*)d_in[6];
    const float* bq = (const float*)d_in[7];
    const float* Wk = (const float*)d_in[8];
    const float* bk = (const float*)d_in[9];
    const float* Wv = (const float*)d_in[10];
    const float* bv = (const float*)d_in[11];
    float* out = (float*)d_out;

    __half *xc, *wqk, *wvt, *qk, *vt, *e;
    float *rinv, *bqk, *csi;
    cudaGetSymbolAddress((void**)&xc,   g_xc);
    cudaGetSymbolAddress((void**)&wqk,  g_wqk);
    cudaGetSymbolAddress((void**)&wvt,  g_wvt);
    cudaGetSymbolAddress((void**)&qk,   g_qk);
    cudaGetSymbolAddress((void**)&vt,   g_vt);
    cudaGetSymbolAddress((void**)&e,    g_e);
    cudaGetSymbolAddress((void**)&rinv, g_rinv);
    cudaGetSymbolAddress((void**)&bqk,  g_bqk);
    cudaGetSymbolAddress((void**)&csi,  g_csi);

    cudaFuncSetAttribute(gemm_h, cudaFuncAttributeMaxDynamicSharedMemorySize, GEMM_DSMEM);

    // one-time stream/event creation (host-side resources only; no device memory)
    static cudaStream_t s2 = nullptr;
    static cudaEvent_t evFork = nullptr, evJoin = nullptr;
    if (!s2) {
        cudaStreamCreateWithFlags(&s2, cudaStreamNonBlocking);
        cudaEventCreateWithFlags(&evFork, cudaEventDisableTiming);
        cudaEventCreateWithFlags(&evJoin, cudaEventDisableTiming);
    }

    // unified prep: LN + weight transposes + bias pack
    prep_kernel<<<LN_BLOCKS + TS_BLOCKS + 1, 256>>>(
        inputs, context, gin, bin, gctx, bctx, Wq, Wk, Wv, bq, bk);

    // q & k in one batched GEMM: z=0 -> q(xn,Wq,bq), z=1 -> k(cn,Wk,bk)
    {
        dim3 grid(DIM / 128, NR / 256, 2);
        gemm_h<<<grid, 256, GEMM_DSMEM>>>(xc, wqk, NR, DIM, DIM,
                                          (size_t)NR * DIM, (size_t)DIM * DIM,
                                          (size_t)NR * DIM,
                                          1.0f, bqk, DIM, nullptr, nullptr,
                                          nullptr, 0, nullptr, qk, 5);
    }

    // E = exp(scale * q @ k^T) fp16 + fused column sums
    {
        float scale = 1.0f / sqrtf((float)DIM);
        dim3 grid(SEQ / 128, SEQ / 256, BATCH);
        gemm_h<<<grid, 256, GEMM_DSMEM>>>(qk, qk + (size_t)NR * DIM, SEQ, SEQ, DIM,
                                          (size_t)SEQ * DIM, (size_t)SEQ * DIM,
                                          (size_t)SEQ * SEQ, scale,
                                          nullptr, 0, nullptr, nullptr,
                                          nullptr, 0, nullptr, e, 6);
    }

    // csi = 1/colsum
    colstats2_kernel<<<dim3(SEQ / 256, BATCH), 256>>>();

    // fork: vt' GEMM on s2 concurrent with rowsum on main stream
    cudaEventRecord(evFork, 0);
    cudaStreamWaitEvent(s2, evFork, 0);
    {
        dim3 grid(SEQ / 128, DIM / 256, BATCH);
        gemm_h<<<grid, 256, GEMM_DSMEM, s2>>>(wvt, xc + (size_t)NR * DIM, DIM, SEQ, DIM,
                                              0, (size_t)SEQ * DIM, (size_t)DIM * SEQ,
                                              1.0f, nullptr, 0, bv, nullptr,
                                              csi, SEQ, nullptr, vt, 5);
    }
    cudaEventRecord(evJoin, s2);

    // rinv[i] = 1 / sum_j E[i,j]*csi[j]  (main stream, concurrent with vt')
    rowsum_kernel<<<dim3(SEQ, BATCH), 256>>>();

    cudaStreamWaitEvent(0, evJoin, 0);

    // out = rinv[i] * (E @ vt'^T) (M=2048, N=512, Kc=2048, batched)
    {
        dim3 grid(DIM / 128, SEQ / 256, BATCH);
        gemm_h<<<grid, 256, GEMM_DSMEM>>>(e, vt, SEQ, DIM, SEQ,
                                          (size_t)SEQ * SEQ, (size_t)DIM * SEQ,
                                          (size_t)SEQ * DIM, 1.0f,
                                          nullptr, 0, nullptr, rinv,
                                          nullptr, 0, out, nullptr, 0);
    }
}

// round 15
// speedup vs baseline: 1.0326x; 1.0326x over previous
#include <cuda_runtime.h>
#include <cuda_fp16.h>
#include <math.h>
#include <stdint.h>

#define BATCH 8
#define SEQ   2048
#define DIM   512
#define NCHUNK 8          // 256-row chunks of SEQ (dots M-tiles)
#define NR    (BATCH * SEQ)
#define LN_BLOCKS (NR)            // 2*NR rows, 2 rows per block
#define TS_BLOCKS 768             // 3 weights x 256 tiles

static const float LN_EPS_F = 1e-5f;

// ---------------- scratch (static device globals; no allocation) ----------------
__device__ __align__(256) __half g_xc [(size_t)2 * NR * DIM];   // [xn | cn]
__device__ __align__(256) __half g_wqk[(size_t)2 * DIM * DIM];  // [Wq^T | Wk^T]
__device__ __align__(256) __half g_wvt[(size_t)DIM * DIM];
__device__ __align__(256) __half g_qk [(size_t)2 * NR * DIM];   // [q | k]
__device__ __align__(256) __half g_vt [(size_t)BATCH * DIM * SEQ];  // vt' = vt * csi
__device__ __align__(256) __half g_e  [(size_t)BATCH * SEQ * SEQ];  // E = exp(dots*scale)
__device__ float g_ps  [BATCH * NCHUNK * SEQ];
__device__ float g_csi [BATCH * SEQ];
__device__ float g_rinv[BATCH * SEQ];
__device__ float g_bqk [2 * DIM];

// ---------------- PTX helpers (baseline compute_103-safe) ----------------
__device__ __forceinline__ uint32_t smem_u32(const void* p) {
    uint32_t a;
    asm("{ .reg .u64 t; cvta.to.shared.u64 t, %1; cvt.u32.u64 %0, t; }" : "=r"(a) : "l"(p));
    return a;
}
__device__ __forceinline__ void cp_async16(uint32_t d, const void* g) {
    asm volatile("cp.async.cg.shared.global [%0], [%1], 16;" :: "r"(d), "l"(g));
}
__device__ __forceinline__ void cp_commit() {
    asm volatile("cp.async.commit_group;" ::: "memory");
}
template <int N>
__device__ __forceinline__ void cp_wait() {
    asm volatile("cp.async.wait_group %0;" :: "n"(N) : "memory");
}
__device__ __forceinline__ void ldsm4(uint32_t& r0, uint32_t& r1, uint32_t& r2, uint32_t& r3,
                                      uint32_t addr) {
    asm volatile("ldmatrix.sync.aligned.m8n8.x4.shared.b16 {%0,%1,%2,%3}, [%4];"
                 : "=r"(r0), "=r"(r1), "=r"(r2), "=r"(r3) : "r"(addr));
}
__device__ __forceinline__ void mma16816(float* c, const uint32_t* a, uint32_t b0, uint32_t b1) {
    asm volatile(
        "mma.sync.aligned.m16n8k16.row.col.f32.f16.f16.f32 "
        "{%0,%1,%2,%3}, {%4,%5,%6,%7}, {%8,%9}, {%0,%1,%2,%3};"
        : "+f"(c[0]), "+f"(c[1]), "+f"(c[2]), "+f"(c[3])
        : "r"(a[0]), "r"(a[1]), "r"(a[2]), "r"(a[3]), "r"(b0), "r"(b1));
}

// ---------------- HMMA plain-fp16 GEMM, CTA tile 256x128, warp tile 64x64 ----
// C[M,N] = A[M,Kc] @ B[N,Kc]^T  (A,B fp16 K-major); M%256==0, N%128==0, Kc%32==0
// pattern 0: outf = (acc*alpha + bias_col + bias_row) * rowscale[z*M+row]
// pattern 5: outh = fp16((acc*alpha + bias_col + bias_row) * colscale)
// pattern 6: outh = fp16(exp(acc*alpha)); fused column sums -> g_ps (per 256-row chunk)
// pattern 7: like 5 but colscale computed inline: cs[col] = 1/sum_c g_ps[(z*NCHUNK+c)*SEQ+col]
// bias_col[z*bias_zs + col]; colscale[z*cs_zs + col]
#define BK 32
#define STAGES 5
#define A_STAGE (256 * 80)
#define B_STAGE (128 * 80)
#define STAGE_BYTES (A_STAGE + B_STAGE)
#define GEMM_DSMEM (STAGES * STAGE_BYTES)

__global__ void __launch_bounds__(256, 1) gemm_h(
    const __half* __restrict__ A, const __half* __restrict__ B,
    int M, int N, int Kc,
    size_t sA, size_t sB, size_t sC,
    float alpha,
    const float* __restrict__ bias_col, int bias_zs,
    const float* __restrict__ bias_row,
    const float* __restrict__ rowscale,
    const float* __restrict__ colscale, int cs_zs,
    float* __restrict__ outf, __half* __restrict__ outh, int pattern)
{
    extern __shared__ char dyn[];
    __shared__ float csbuf[128];
    uint32_t dynb = smem_u32(dyn);

    int z = blockIdx.z;
    const __half* Ab = A + (size_t)z * sA + (size_t)(blockIdx.y * 256) * Kc;
    const __half* Bb = B + (size_t)z * sB + (size_t)(blockIdx.x * 128) * Kc;
    int bm = blockIdx.y * 256;
    int bn = blockIdx.x * 128;

    int t = threadIdx.x;
    int wid = t >> 5, lane = t & 31;
    int wm = wid & 3;        // 4 warps over M (64 rows each)
    int wn = wid >> 2;       // 2 warps over N (64 cols each)

    // pattern 7 prologue: inline csi for this CTA's 128 columns (of N=SEQ)
    if (pattern == 7 && t < 128) {
        int col = bn + t;
        float s = 0.0f;
        #pragma unroll
        for (int c = 0; c < NCHUNK; c++)
            s += g_ps[((size_t)z * NCHUNK + c) * SEQ + col];
        csbuf[t] = 1.0f / s;
    }

    float acc[4][8][4];
    #pragma unroll
    for (int i = 0; i < 4; i++)
        #pragma unroll
        for (int j = 0; j < 8; j++)
            #pragma unroll
            for (int r = 0; r < 4; r++) acc[i][j][r] = 0.0f;

    int nkb = Kc / BK;

    auto issue = [&](int kb) {
        int slot = kb % STAGES;
        uint32_t sa = dynb + slot * STAGE_BYTES;
        uint32_t sb = sa + A_STAGE;
        int kh = kb * BK;
        #pragma unroll
        for (int i = 0; i < 4; i++) {           // A: 256 rows x 32 k
            int idx = t + 256 * i;
            int row = idx >> 2, c = idx & 3;
            cp_async16(sa + row * 80 + c * 16, Ab + (size_t)row * Kc + kh + c * 8);
        }
        #pragma unroll
        for (int i = 0; i < 2; i++) {           // B: 128 rows x 32 k
            int idx = t + 256 * i;
            int row = idx >> 2, c = idx & 3;
            cp_async16(sb + row * 80 + c * 16, Bb + (size_t)row * Kc + kh + c * 8);
        }
    };

    issue(0); cp_commit();
    issue(1); cp_commit();
    issue(2); cp_commit();
    issue(3); cp_commit();

    uint32_t a_lane = (uint32_t)((wm * 64 + (lane & 15)) * 80 + ((lane >> 4) * 8) * 2);
    uint32_t b_lane = (uint32_t)(A_STAGE +
                       (wn * 64 + (lane & 7) + (lane >> 4) * 8) * 80 +
                       (((lane >> 3) & 1) * 8) * 2);

    cp_wait<2>();          // slots 0 and 1 ready
    __syncthreads();

    uint32_t af[2][4][4];  // A fragments, double buffered (4 x m16)
    uint32_t bf[2][4][4];  // B fragments, double buffered (4 x n16)

    {
        uint32_t s0 = dynb;
        #pragma unroll
        for (int mi = 0; mi < 4; mi++)
            ldsm4(af[0][mi][0], af[0][mi][1], af[0][mi][2], af[0][mi][3],
                  s0 + a_lane + mi * (16 * 80));
        #pragma unroll
        for (int g = 0; g < 4; g++)
            ldsm4(bf[0][g][0], bf[0][g][1], bf[0][g][2], bf[0][g][3],
                  s0 + b_lane + g * (16 * 80));
    }

    int p = 0;
    for (int kb = 0; kb < nkb; kb++) {
        if (kb + 4 < nkb) issue(kb + 4);
        cp_commit();
        uint32_t scur = dynb + (kb % STAGES) * STAGE_BYTES;
        uint32_t snxt = dynb + ((kb + 1) % STAGES) * STAGE_BYTES;

        // ---- ks = 0: prefetch (kb, ks1) into p^1, mma on p ----
        #pragma unroll
        for (int mi = 0; mi < 4; mi++)
            ldsm4(af[p^1][mi][0], af[p^1][mi][1], af[p^1][mi][2], af[p^1][mi][3],
                  scur + a_lane + mi * (16 * 80) + 32);
        #pragma unroll
        for (int g = 0; g < 4; g++)
            ldsm4(bf[p^1][g][0], bf[p^1][g][1], bf[p^1][g][2], bf[p^1][g][3],
                  scur + b_lane + g * (16 * 80) + 32);
        #pragma unroll
        for (int mi = 0; mi < 4; mi++)
            #pragma unroll
            for (int ni = 0; ni < 8; ni++)
                mma16816(acc[mi][ni], af[p][mi],
                         bf[p][ni >> 1][(ni & 1) * 2], bf[p][ni >> 1][(ni & 1) * 2 + 1]);
        p ^= 1;

        // ---- ks = 1: prefetch (kb+1, ks0) into p^1, mma on p ----
        if (kb + 1 < nkb) {
            #pragma unroll
            for (int mi = 0; mi < 4; mi++)
                ldsm4(af[p^1][mi][0], af[p^1][mi][1], af[p^1][mi][2], af[p^1][mi][3],
                      snxt + a_lane + mi * (16 * 80));
            #pragma unroll
            for (int g = 0; g < 4; g++)
                ldsm4(bf[p^1][g][0], bf[p^1][g][1], bf[p^1][g][2], bf[p^1][g][3],
                      snxt + b_lane + g * (16 * 80));
        }
        #pragma unroll
        for (int mi = 0; mi < 4; mi++)
            #pragma unroll
            for (int ni = 0; ni < 8; ni++)
                mma16816(acc[mi][ni], af[p][mi],
                         bf[p][ni >> 1][(ni & 1) * 2], bf[p][ni >> 1][(ni & 1) * 2 + 1]);
        p ^= 1;

        cp_wait<2>();
        __syncthreads();
    }

    // ---------------- store epilogue ----------------
    int r_lane = lane >> 2;
    int c_lane = (lane & 3) * 2;

    if (pattern == 6) {
        float csum[8][2];
        #pragma unroll
        for (int ni = 0; ni < 8; ni++) { csum[ni][0] = 0.0f; csum[ni][1] = 0.0f; }

        #pragma unroll
        for (int mi = 0; mi < 4; mi++) {
            #pragma unroll
            for (int ni = 0; ni < 8; ni++) {
                int row = bm + wm * 64 + mi * 16 + r_lane;
                int col = bn + wn * 64 + ni * 8 + c_lane;
                float* a4 = acc[mi][ni];
                #pragma unroll
                for (int h = 0; h < 2; h++) {
                    int rr = row + h * 8;
                    float e0 = __expf(a4[h * 2 + 0] * alpha);
                    float e1 = __expf(a4[h * 2 + 1] * alpha);
                    csum[ni][0] += e0;
                    csum[ni][1] += e1;
                    __half2 hh = __halves2half2(__float2half_rn(e0), __float2half_rn(e1));
                    *(__half2*)(outh + (size_t)z * sC + (size_t)rr * N + col) = hh;
                }
            }
        }
        // reduce over the 8 lane-rows (lane bits 2..4)
        #pragma unroll
        for (int o = 4; o < 32; o <<= 1)
            #pragma unroll
            for (int ni = 0; ni < 8; ni++) {
                csum[ni][0] += __shfl_xor_sync(0xffffffffu, csum[ni][0], o);
                csum[ni][1] += __shfl_xor_sync(0xffffffffu, csum[ni][1], o);
            }
        cp_wait<0>();
        __syncthreads();
        float* ssm = (float*)dyn;            // [4][128]
        if ((lane >> 2) == 0) {
            #pragma unroll
            for (int ni = 0; ni < 8; ni++) {
                int col = wn * 64 + ni * 8 + (lane & 3) * 2;
                ssm[wm * 128 + col]     = csum[ni][0];
                ssm[wm * 128 + col + 1] = csum[ni][1];
            }
        }
        __syncthreads();
        if (t < 128) {
            float s = ssm[t] + ssm[128 + t] + ssm[256 + t] + ssm[384 + t];
            g_ps[((size_t)z * NCHUNK + blockIdx.y) * SEQ + bn + t] = s;
        }
        return;
    }

    #pragma unroll
    for (int mi = 0; mi < 4; mi++) {
        #pragma unroll
        for (int ni = 0; ni < 8; ni++) {
            int row = bm + wm * 64 + mi * 16 + r_lane;
            int col = bn + wn * 64 + ni * 8 + c_lane;
            float* a4 = acc[mi][ni];
            float bc0 = bias_col ? bias_col[z * bias_zs + col]     : 0.0f;
            float bc1 = bias_col ? bias_col[z * bias_zs + col + 1] : 0.0f;
            float cs0 = 1.0f, cs1 = 1.0f;
            if (pattern == 7) {
                cs0 = csbuf[col - bn];
                cs1 = csbuf[col - bn + 1];
            } else if (colscale) {
                cs0 = colscale[z * cs_zs + col];
                cs1 = colscale[z * cs_zs + col + 1];
            }
            #pragma unroll
            for (int h = 0; h < 2; h++) {
                int rr = row + h * 8;
                float br = bias_row ? bias_row[rr] : 0.0f;
                float v0 = (a4[h * 2 + 0] * alpha + bc0 + br) * cs0;
                float v1 = (a4[h * 2 + 1] * alpha + bc1 + br) * cs1;
                if (pattern == 0) {
                    float rs = rowscale ? rowscale[(size_t)z * M + rr] : 1.0f;
                    float2 o = make_float2(v0 * rs, v1 * rs);
                    *(float2*)(outf + (size_t)z * sC + (size_t)rr * N + col) = o;
                } else {  // pattern 5 / 7: fp16
                    __half2 hh = __halves2half2(__float2half_rn(v0), __float2half_rn(v1));
                    *(__half2*)(outh + (size_t)z * sC + (size_t)rr * N + col) = hh;
                }
            }
        }
    }
}

// ---------------- unified prep: LN (2 rows/block) + 3 weight transposes + bias pack ----
__global__ void __launch_bounds__(256) prep_kernel(
    const float* __restrict__ xin, const float* __restrict__ cin,
    const float* __restrict__ gx, const float* __restrict__ bx,
    const float* __restrict__ gc, const float* __restrict__ bc,
    const float* __restrict__ Wq, const float* __restrict__ Wk,
    const float* __restrict__ Wv,
    const float* __restrict__ bq, const float* __restrict__ bk)
{
    int blk = blockIdx.x;
    if (blk < LN_BLOCKS) {
        // two LN rows per block: rows 2*blk, 2*blk+1 of combined [x | c]
        __shared__ float sh[2][8];
        int half = threadIdx.x >> 7;      // 0 or 1
        int t = threadIdx.x & 127;
        int row = blk * 2 + half;         // 0 .. 2*NR-1
        const float* x;
        const float* g;
        const float* b;
        __half* y;
        if (row < NR) {
            x = xin + (size_t)row * DIM; g = gx; b = bx;
            y = g_xc + (size_t)row * DIM;
        } else {
            int r2 = row - NR;
            x = cin + (size_t)r2 * DIM; g = gc; b = bc;
            y = g_xc + (size_t)NR * DIM + (size_t)r2 * DIM;
        }
        float4 v = ((const float4*)x)[t];
        float s  = v.x + v.y + v.z + v.w;
        float ss = v.x*v.x + v.y*v.y + v.z*v.z + v.w*v.w;
        #pragma unroll
        for (int o = 16; o > 0; o >>= 1) {
            s  += __shfl_down_sync(0xffffffffu, s, o);
            ss += __shfl_down_sync(0xffffffffu, ss, o);
        }
        if ((t & 31) == 0) { sh[half][t >> 5] = s; sh[half][4 + (t >> 5)] = ss; }
        __syncthreads();
        float fs  = sh[half][0] + sh[half][1] + sh[half][2] + sh[half][3];
        float fss = sh[half][4] + sh[half][5] + sh[half][6] + sh[half][7];
        float mu  = fs * (1.0f / DIM);
        float var = fss * (1.0f / DIM) - mu * mu;
        float rstd = rsqrtf(var + LN_EPS_F);
        float4 gv = ((const float4*)g)[t];
        float4 bv = ((const float4*)b)[t];
        float o0 = (v.x - mu) * rstd * gv.x + bv.x;
        float o1 = (v.y - mu) * rstd * gv.y + bv.y;
        float o2 = (v.z - mu) * rstd * gv.z + bv.z;
        float o3 = (v.w - mu) * rstd * gv.w + bv.w;
        ((__half2*)(y + t * 4))[0] = __halves2half2(__float2half_rn(o0), __float2half_rn(o1));
        ((__half2*)(y + t * 4))[1] = __halves2half2(__float2half_rn(o2), __float2half_rn(o3));
    } else if (blk < LN_BLOCKS + TS_BLOCKS) {
        // weight transpose tiles
        __shared__ float tile[32][33];
        int idx = blk - LN_BLOCKS;
        int which = idx >> 8;      // 0..2
        int tl = idx & 255;        // 16x16 tiles
        const float* in = (which == 0) ? Wq : (which == 1) ? Wk : Wv;
        __half* out = (which == 0) ? g_wqk
                    : (which == 1) ? (g_wqk + (size_t)DIM * DIM) : g_wvt;
        int r0 = (tl >> 4) * 32, c0 = (tl & 15) * 32;
        int tx = threadIdx.x & 31, ty = threadIdx.x >> 5;
        #pragma unroll
        for (int i = ty; i < 32; i += 8)
            tile[i][tx] = in[(size_t)(r0 + i) * DIM + c0 + tx];
        __syncthreads();
        #pragma unroll
        for (int i = ty; i < 32; i += 8)
            out[(size_t)(c0 + i) * DIM + r0 + tx] = __float2half_rn(tile[tx][i]);
    } else {
        // bias pack
        for (int t = threadIdx.x; t < DIM; t += 256) {
            g_bqk[t] = bq[t];
            g_bqk[DIM + t] = bk[t];
        }
    }
}

// ---------------- column sums combine -> 1/colsum ----------------
__global__ void __launch_bounds__(256) colstats2_kernel() {
    int j = blockIdx.x * 256 + threadIdx.x;
    int z = blockIdx.y;
    float s = 0.0f;
    #pragma unroll
    for (int c = 0; c < NCHUNK; c++)
        s += g_ps[((size_t)z * NCHUNK + c) * SEQ + j];
    g_csi[(size_t)z * SEQ + j] = 1.0f / s;
}

// ---------------- rowsum: rinv[i] = 1 / sum_j E[i,j]*csi[j] (read-only over E) ----
__global__ void __launch_bounds__(256) rowsum_kernel() {
    int i = blockIdx.x;
    int z = blockIdx.y;
    int t = threadIdx.x;
    const __half* row = g_e + ((size_t)z * SEQ + i) * SEQ;
    const float* ci = g_csi + (size_t)z * SEQ;
    float acc = 0.0f;
    #pragma unroll
    for (int j2 = t; j2 < SEQ / 2; j2 += 256) {
        int j = j2 * 2;
        __half2 e2 = *(const __half2*)(row + j);
        float2 c2 = *(const float2*)(ci + j);
        acc += __half2float(__low2half(e2))  * c2.x
             + __half2float(__high2half(e2)) * c2.y;
    }
    __shared__ float sh[8];
    #pragma unroll
    for (int o = 16; o > 0; o >>= 1)
        acc += __shfl_down_sync(0xffffffffu, acc, o);
    if ((t & 31) == 0) sh[t >> 5] = acc;
    __syncthreads();
    if (t == 0) {
        float s = 0.0f;
        #pragma unroll
        for (int w = 0; w < 8; w++) s += sh[w];
        g_rinv[(size_t)z * SEQ + i] = 1.0f / s;
    }
}

// ---------------- launch ----------------
extern "C" void kernel_launch(void* const* d_in, const int* in_sizes, int n_in,
                              void* d_out, int out_size) {
    const float* inputs  = (const float*)d_in[0];
    const float* context = (const float*)d_in[1];
    const float* gin  = (const float*)d_in[2];
    const float* bin  = (const float*)d_in[3];
    const float* gctx = (const float*)d_in[4];
    const float* bctx = (const float*)d_in[5];
    const float* Wq = (const float*)d_in[6];
    const float* bq = (const float*)d_in[7];
    const float* Wk = (const float*)d_in[8];
    const float* bk = (const float*)d_in[9];
    const float* Wv = (const float*)d_in[10];
    const float* bv = (const float*)d_in[11];
    float* out = (float*)d_out;

    __half *xc, *wqk, *wvt, *qk, *vt, *e;
    float *rinv, *bqk;
    cudaGetSymbolAddress((void**)&xc,   g_xc);
    cudaGetSymbolAddress((void**)&wqk,  g_wqk);
    cudaGetSymbolAddress((void**)&wvt,  g_wvt);
    cudaGetSymbolAddress((void**)&qk,   g_qk);
    cudaGetSymbolAddress((void**)&vt,   g_vt);
    cudaGetSymbolAddress((void**)&e,    g_e);
    cudaGetSymbolAddress((void**)&rinv, g_rinv);
    cudaGetSymbolAddress((void**)&bqk,  g_bqk);

    cudaFuncSetAttribute(gemm_h, cudaFuncAttributeMaxDynamicSharedMemorySize, GEMM_DSMEM);

    // one-time stream/event creation (host-side resources only; no device memory)
    static cudaStream_t s2 = nullptr;
    static cudaEvent_t evFork = nullptr, evJoin = nullptr;
    if (!s2) {
        cudaStreamCreateWithFlags(&s2, cudaStreamNonBlocking);
        cudaEventCreateWithFlags(&evFork, cudaEventDisableTiming);
        cudaEventCreateWithFlags(&evJoin, cudaEventDisableTiming);
    }

    // unified prep: LN + weight transposes + bias pack
    prep_kernel<<<LN_BLOCKS + TS_BLOCKS + 1, 256>>>(
        inputs, context, gin, bin, gctx, bctx, Wq, Wk, Wv, bq, bk);

    // q & k in one batched GEMM: z=0 -> q(xn,Wq,bq), z=1 -> k(cn,Wk,bk)
    {
        dim3 grid(DIM / 128, NR / 256, 2);
        gemm_h<<<grid, 256, GEMM_DSMEM>>>(xc, wqk, NR, DIM, DIM,
                                          (size_t)NR * DIM, (size_t)DIM * DIM,
                                          (size_t)NR * DIM,
                                          1.0f, bqk, DIM, nullptr, nullptr,
                                          nullptr, 0, nullptr, qk, 5);
    }

    // E = exp(scale * q @ k^T) fp16 + fused column sums -> g_ps
    {
        float scale = 1.0f / sqrtf((float)DIM);
        dim3 grid(SEQ / 128, SEQ / 256, BATCH);
        gemm_h<<<grid, 256, GEMM_DSMEM>>>(qk, qk + (size_t)NR * DIM, SEQ, SEQ, DIM,
                                          (size_t)SEQ * DIM, (size_t)SEQ * DIM,
                                          (size_t)SEQ * SEQ, scale,
                                          nullptr, 0, nullptr, nullptr,
                                          nullptr, 0, nullptr, e, 6);
    }

    // fork immediately after E: vt' (inline csi from g_ps) on s2,
    // colstats2 + rowsum on main stream
    cudaEventRecord(evFork, 0);
    cudaStreamWaitEvent(s2, evFork, 0);
    {
        dim3 grid(SEQ / 128, DIM / 256, BATCH);
        gemm_h<<<grid, 256, GEMM_DSMEM, s2>>>(wvt, xc + (size_t)NR * DIM, DIM, SEQ, DIM,
                                              0, (size_t)SEQ * DIM, (size_t)DIM * SEQ,
                                              1.0f, nullptr, 0, bv, nullptr,
                                              nullptr, 0, nullptr, vt, 7);
    }
    cudaEventRecord(evJoin, s2);

    // main stream: csi = 1/colsum ; rinv[i] = 1 / sum_j E[i,j]*csi[j]
    colstats2_kernel<<<dim3(SEQ / 256, BATCH), 256>>>();
    rowsum_kernel<<<dim3(SEQ, BATCH), 256>>>();

    cudaStreamWaitEvent(0, evJoin, 0);

    // out = rinv[i] * (E @ vt'^T) (M=2048, N=512, Kc=2048, batched)
    {
        dim3 grid(DIM / 128, SEQ / 256, BATCH);
        gemm_h<<<grid, 256, GEMM_DSMEM>>>(e, vt, SEQ, DIM, SEQ,
                                          (size_t)SEQ * SEQ, (size_t)DIM * SEQ,
                                          (size_t)SEQ * DIM, 1.0f,
                                          nullptr, 0, nullptr, rinv,
                                          nullptr, 0, out, nullptr, 0);
    }
}

// round 16
// speedup vs baseline: 1.0573x; 1.0239x over previous
#include <cuda_runtime.h>
#include <cuda_fp16.h>
#include <math.h>
#include <stdint.h>

#define BATCH 8
#define SEQ   2048
#define DIM   512
#define NCHUNK 8          // 256-row chunks of SEQ (dots M-tiles)
#define NR    (BATCH * SEQ)
#define LN_BLOCKS (NR)            // 2*NR rows, 2 rows per block
#define TS_BLOCKS 768             // 3 weights x 256 tiles

static const float LN_EPS_F = 1e-5f;

// ---------------- scratch (static device globals; no allocation) ----------------
__device__ __align__(256) __half g_xc [(size_t)2 * NR * DIM];   // [xn | cn]
__device__ __align__(256) __half g_wqk[(size_t)2 * DIM * DIM];  // [Wq^T | Wk^T]
__device__ __align__(256) __half g_wvt[(size_t)DIM * DIM];
__device__ __align__(256) __half g_qk [(size_t)2 * NR * DIM];   // [q | k]
__device__ __align__(256) __half g_vt [(size_t)BATCH * DIM * SEQ];  // vt' = vt * csi
__device__ __align__(256) __half g_e  [(size_t)BATCH * SEQ * SEQ];  // E = exp(dots*scale)
__device__ float g_ps  [BATCH * NCHUNK * SEQ];
__device__ float g_csi [BATCH * SEQ];
__device__ float g_rinv[BATCH * SEQ];
__device__ float g_bqk [2 * DIM];

// ---------------- PTX helpers (baseline compute_103-safe) ----------------
__device__ __forceinline__ uint32_t smem_u32(const void* p) {
    uint32_t a;
    asm("{ .reg .u64 t; cvta.to.shared.u64 t, %1; cvt.u32.u64 %0, t; }" : "=r"(a) : "l"(p));
    return a;
}
__device__ __forceinline__ void cp_async16(uint32_t d, const void* g) {
    asm volatile("cp.async.cg.shared.global [%0], [%1], 16;" :: "r"(d), "l"(g));
}
__device__ __forceinline__ void cp_commit() {
    asm volatile("cp.async.commit_group;" ::: "memory");
}
template <int N>
__device__ __forceinline__ void cp_wait() {
    asm volatile("cp.async.wait_group %0;" :: "n"(N) : "memory");
}
__device__ __forceinline__ void ldsm4(uint32_t& r0, uint32_t& r1, uint32_t& r2, uint32_t& r3,
                                      uint32_t addr) {
    asm volatile("ldmatrix.sync.aligned.m8n8.x4.shared.b16 {%0,%1,%2,%3}, [%4];"
                 : "=r"(r0), "=r"(r1), "=r"(r2), "=r"(r3) : "r"(addr));
}
__device__ __forceinline__ void mma16816(float* c, const uint32_t* a, uint32_t b0, uint32_t b1) {
    asm volatile(
        "mma.sync.aligned.m16n8k16.row.col.f32.f16.f16.f32 "
        "{%0,%1,%2,%3}, {%4,%5,%6,%7}, {%8,%9}, {%0,%1,%2,%3};"
        : "+f"(c[0]), "+f"(c[1]), "+f"(c[2]), "+f"(c[3])
        : "r"(a[0]), "r"(a[1]), "r"(a[2]), "r"(a[3]), "r"(b0), "r"(b1));
}

// ---------------- HMMA plain-fp16 GEMM, CTA tile 256x128, warp tile 64x64 ----
// Compile-time PATTERN specialization:
// 0: outf = (acc*alpha + bias_col + bias_row) * rowscale[z*M+row]
// 5: outh = fp16((acc*alpha + bias_col + bias_row) * colscale)
// 6: outh = fp16(exp(acc*alpha)); fused column sums -> g_ps (per 256-row chunk)
// 7: like 5 but colscale computed inline from g_ps
#define BK 32
#define STAGES 5
#define A_STAGE (256 * 80)
#define B_STAGE (128 * 80)
#define STAGE_BYTES (A_STAGE + B_STAGE)
#define GEMM_DSMEM (STAGES * STAGE_BYTES)

template <int PATTERN>
__global__ void __launch_bounds__(256, 1) gemm_h(
    const __half* __restrict__ A, const __half* __restrict__ B,
    int M, int N, int Kc,
    size_t sA, size_t sB, size_t sC,
    float alpha,
    const float* __restrict__ bias_col, int bias_zs,
    const float* __restrict__ bias_row,
    const float* __restrict__ rowscale,
    const float* __restrict__ colscale, int cs_zs,
    float* __restrict__ outf, __half* __restrict__ outh)
{
    extern __shared__ char dyn[];
    __shared__ float csbuf[128];
    uint32_t dynb = smem_u32(dyn);

    int z = blockIdx.z;
    const __half* Ab = A + (size_t)z * sA + (size_t)(blockIdx.y * 256) * Kc;
    const __half* Bb = B + (size_t)z * sB + (size_t)(blockIdx.x * 128) * Kc;
    int bm = blockIdx.y * 256;
    int bn = blockIdx.x * 128;

    int t = threadIdx.x;
    int wid = t >> 5, lane = t & 31;
    int wm = wid & 3;        // 4 warps over M (64 rows each)
    int wn = wid >> 2;       // 2 warps over N (64 cols each)

    // PATTERN 7 prologue: inline csi for this CTA's 128 columns (of N=SEQ)
    if (PATTERN == 7 && t < 128) {
        int col = bn + t;
        float s = 0.0f;
        #pragma unroll
        for (int c = 0; c < NCHUNK; c++)
            s += g_ps[((size_t)z * NCHUNK + c) * SEQ + col];
        csbuf[t] = 1.0f / s;
    }

    float acc[4][8][4];
    #pragma unroll
    for (int i = 0; i < 4; i++)
        #pragma unroll
        for (int j = 0; j < 8; j++)
            #pragma unroll
            for (int r = 0; r < 4; r++) acc[i][j][r] = 0.0f;

    int nkb = Kc / BK;

    auto issue = [&](int kb) {
        int slot = kb % STAGES;
        uint32_t sa = dynb + slot * STAGE_BYTES;
        uint32_t sb = sa + A_STAGE;
        int kh = kb * BK;
        #pragma unroll
        for (int i = 0; i < 4; i++) {           // A: 256 rows x 32 k
            int idx = t + 256 * i;
            int row = idx >> 2, c = idx & 3;
            cp_async16(sa + row * 80 + c * 16, Ab + (size_t)row * Kc + kh + c * 8);
        }
        #pragma unroll
        for (int i = 0; i < 2; i++) {           // B: 128 rows x 32 k
            int idx = t + 256 * i;
            int row = idx >> 2, c = idx & 3;
            cp_async16(sb + row * 80 + c * 16, Bb + (size_t)row * Kc + kh + c * 8);
        }
    };

    issue(0); cp_commit();
    issue(1); cp_commit();
    issue(2); cp_commit();
    issue(3); cp_commit();

    uint32_t a_lane = (uint32_t)((wm * 64 + (lane & 15)) * 80 + ((lane >> 4) * 8) * 2);
    uint32_t b_lane = (uint32_t)(A_STAGE +
                       (wn * 64 + (lane & 7) + (lane >> 4) * 8) * 80 +
                       (((lane >> 3) & 1) * 8) * 2);

    cp_wait<2>();          // slots 0 and 1 ready
    __syncthreads();

    uint32_t af[2][4][4];  // A fragments, double buffered (4 x m16)
    uint32_t bf[2][4][4];  // B fragments, double buffered (4 x n16)

    {
        uint32_t s0 = dynb;
        #pragma unroll
        for (int mi = 0; mi < 4; mi++)
            ldsm4(af[0][mi][0], af[0][mi][1], af[0][mi][2], af[0][mi][3],
                  s0 + a_lane + mi * (16 * 80));
        #pragma unroll
        for (int g = 0; g < 4; g++)
            ldsm4(bf[0][g][0], bf[0][g][1], bf[0][g][2], bf[0][g][3],
                  s0 + b_lane + g * (16 * 80));
    }

    int p = 0;
    for (int kb = 0; kb < nkb; kb++) {
        if (kb + 4 < nkb) issue(kb + 4);
        cp_commit();
        uint32_t scur = dynb + (kb % STAGES) * STAGE_BYTES;
        uint32_t snxt = dynb + ((kb + 1) % STAGES) * STAGE_BYTES;

        // ---- ks = 0: prefetch (kb, ks1) into p^1, mma on p ----
        #pragma unroll
        for (int mi = 0; mi < 4; mi++)
            ldsm4(af[p^1][mi][0], af[p^1][mi][1], af[p^1][mi][2], af[p^1][mi][3],
                  scur + a_lane + mi * (16 * 80) + 32);
        #pragma unroll
        for (int g = 0; g < 4; g++)
            ldsm4(bf[p^1][g][0], bf[p^1][g][1], bf[p^1][g][2], bf[p^1][g][3],
                  scur + b_lane + g * (16 * 80) + 32);
        #pragma unroll
        for (int mi = 0; mi < 4; mi++)
            #pragma unroll
            for (int ni = 0; ni < 8; ni++)
                mma16816(acc[mi][ni], af[p][mi],
                         bf[p][ni >> 1][(ni & 1) * 2], bf[p][ni >> 1][(ni & 1) * 2 + 1]);
        p ^= 1;

        // ---- ks = 1: prefetch (kb+1, ks0) into p^1, mma on p ----
        if (kb + 1 < nkb) {
            #pragma unroll
            for (int mi = 0; mi < 4; mi++)
                ldsm4(af[p^1][mi][0], af[p^1][mi][1], af[p^1][mi][2], af[p^1][mi][3],
                      snxt + a_lane + mi * (16 * 80));
            #pragma unroll
            for (int g = 0; g < 4; g++)
                ldsm4(bf[p^1][g][0], bf[p^1][g][1], bf[p^1][g][2], bf[p^1][g][3],
                      snxt + b_lane + g * (16 * 80));
        }
        #pragma unroll
        for (int mi = 0; mi < 4; mi++)
            #pragma unroll
            for (int ni = 0; ni < 8; ni++)
                mma16816(acc[mi][ni], af[p][mi],
                         bf[p][ni >> 1][(ni & 1) * 2], bf[p][ni >> 1][(ni & 1) * 2 + 1]);
        p ^= 1;

        cp_wait<2>();
        __syncthreads();
    }

    // ---------------- store epilogue ----------------
    int r_lane = lane >> 2;
    int c_lane = (lane & 3) * 2;

    if (PATTERN == 6) {
        float csum[8][2];
        #pragma unroll
        for (int ni = 0; ni < 8; ni++) { csum[ni][0] = 0.0f; csum[ni][1] = 0.0f; }

        #pragma unroll
        for (int mi = 0; mi < 4; mi++) {
            #pragma unroll
            for (int ni = 0; ni < 8; ni++) {
                int row = bm + wm * 64 + mi * 16 + r_lane;
                int col = bn + wn * 64 + ni * 8 + c_lane;
                float* a4 = acc[mi][ni];
                #pragma unroll
                for (int h = 0; h < 2; h++) {
                    int rr = row + h * 8;
                    float e0 = __expf(a4[h * 2 + 0] * alpha);
                    float e1 = __expf(a4[h * 2 + 1] * alpha);
                    csum[ni][0] += e0;
                    csum[ni][1] += e1;
                    __half2 hh = __halves2half2(__float2half_rn(e0), __float2half_rn(e1));
                    *(__half2*)(outh + (size_t)z * sC + (size_t)rr * N + col) = hh;
                }
            }
        }
        // reduce over the 8 lane-rows (lane bits 2..4)
        #pragma unroll
        for (int o = 4; o < 32; o <<= 1)
            #pragma unroll
            for (int ni = 0; ni < 8; ni++) {
                csum[ni][0] += __shfl_xor_sync(0xffffffffu, csum[ni][0], o);
                csum[ni][1] += __shfl_xor_sync(0xffffffffu, csum[ni][1], o);
            }
        cp_wait<0>();
        __syncthreads();
        float* ssm = (float*)dyn;            // [4][128]
        if ((lane >> 2) == 0) {
            #pragma unroll
            for (int ni = 0; ni < 8; ni++) {
                int col = wn * 64 + ni * 8 + (lane & 3) * 2;
                ssm[wm * 128 + col]     = csum[ni][0];
                ssm[wm * 128 + col + 1] = csum[ni][1];
            }
        }
        __syncthreads();
        if (t < 128) {
            float s = ssm[t] + ssm[128 + t] + ssm[256 + t] + ssm[384 + t];
            g_ps[((size_t)z * NCHUNK + blockIdx.y) * SEQ + bn + t] = s;
        }
        return;
    }

    #pragma unroll
    for (int mi = 0; mi < 4; mi++) {
        #pragma unroll
        for (int ni = 0; ni < 8; ni++) {
            int row = bm + wm * 64 + mi * 16 + r_lane;
            int col = bn + wn * 64 + ni * 8 + c_lane;
            float* a4 = acc[mi][ni];
            float bc0 = bias_col ? bias_col[z * bias_zs + col]     : 0.0f;
            float bc1 = bias_col ? bias_col[z * bias_zs + col + 1] : 0.0f;
            float cs0 = 1.0f, cs1 = 1.0f;
            if (PATTERN == 7) {
                cs0 = csbuf[col - bn];
                cs1 = csbuf[col - bn + 1];
            } else if (PATTERN == 5 && colscale) {
                cs0 = colscale[z * cs_zs + col];
                cs1 = colscale[z * cs_zs + col + 1];
            }
            #pragma unroll
            for (int h = 0; h < 2; h++) {
                int rr = row + h * 8;
                float br = bias_row ? bias_row[rr] : 0.0f;
                float v0 = (a4[h * 2 + 0] * alpha + bc0 + br) * cs0;
                float v1 = (a4[h * 2 + 1] * alpha + bc1 + br) * cs1;
                if (PATTERN == 0) {
                    float rs = rowscale ? rowscale[(size_t)z * M + rr] : 1.0f;
                    float2 o = make_float2(v0 * rs, v1 * rs);
                    *(float2*)(outf + (size_t)z * sC + (size_t)rr * N + col) = o;
                } else {  // 5 / 7: fp16
                    __half2 hh = __halves2half2(__float2half_rn(v0), __float2half_rn(v1));
                    *(__half2*)(outh + (size_t)z * sC + (size_t)rr * N + col) = hh;
                }
            }
        }
    }
}

// ---------------- unified prep: LN (2 rows/block) + 3 weight transposes + bias pack ----
__global__ void __launch_bounds__(256) prep_kernel(
    const float* __restrict__ xin, const float* __restrict__ cin,
    const float* __restrict__ gx, const float* __restrict__ bx,
    const float* __restrict__ gc, const float* __restrict__ bc,
    const float* __restrict__ Wq, const float* __restrict__ Wk,
    const float* __restrict__ Wv,
    const float* __restrict__ bq, const float* __restrict__ bk)
{
    int blk = blockIdx.x;
    if (blk < LN_BLOCKS) {
        // two LN rows per block: rows 2*blk, 2*blk+1 of combined [x | c]
        __shared__ float sh[2][8];
        int half = threadIdx.x >> 7;      // 0 or 1
        int t = threadIdx.x & 127;
        int row = blk * 2 + half;         // 0 .. 2*NR-1
        const float* x;
        const float* g;
        const float* b;
        __half* y;
        if (row < NR) {
            x = xin + (size_t)row * DIM; g = gx; b = bx;
            y = g_xc + (size_t)row * DIM;
        } else {
            int r2 = row - NR;
            x = cin + (size_t)r2 * DIM; g = gc; b = bc;
            y = g_xc + (size_t)NR * DIM + (size_t)r2 * DIM;
        }
        float4 v = ((const float4*)x)[t];
        float s  = v.x + v.y + v.z + v.w;
        float ss = v.x*v.x + v.y*v.y + v.z*v.z + v.w*v.w;
        #pragma unroll
        for (int o = 16; o > 0; o >>= 1) {
            s  += __shfl_down_sync(0xffffffffu, s, o);
            ss += __shfl_down_sync(0xffffffffu, ss, o);
        }
        if ((t & 31) == 0) { sh[half][t >> 5] = s; sh[half][4 + (t >> 5)] = ss; }
        __syncthreads();
        float fs  = sh[half][0] + sh[half][1] + sh[half][2] + sh[half][3];
        float fss = sh[half][4] + sh[half][5] + sh[half][6] + sh[half][7];
        float mu  = fs * (1.0f / DIM);
        float var = fss * (1.0f / DIM) - mu * mu;
        float rstd = rsqrtf(var + LN_EPS_F);
        float4 gv = ((const float4*)g)[t];
        float4 bv = ((const float4*)b)[t];
        float o0 = (v.x - mu) * rstd * gv.x + bv.x;
        float o1 = (v.y - mu) * rstd * gv.y + bv.y;
        float o2 = (v.z - mu) * rstd * gv.z + bv.z;
        float o3 = (v.w - mu) * rstd * gv.w + bv.w;
        ((__half2*)(y + t * 4))[0] = __halves2half2(__float2half_rn(o0), __float2half_rn(o1));
        ((__half2*)(y + t * 4))[1] = __halves2half2(__float2half_rn(o2), __float2half_rn(o3));
    } else if (blk < LN_BLOCKS + TS_BLOCKS) {
        // weight transpose tiles
        __shared__ float tile[32][33];
        int idx = blk - LN_BLOCKS;
        int which = idx >> 8;      // 0..2
        int tl = idx & 255;        // 16x16 tiles
        const float* in = (which == 0) ? Wq : (which == 1) ? Wk : Wv;
        __half* out = (which == 0) ? g_wqk
                    : (which == 1) ? (g_wqk + (size_t)DIM * DIM) : g_wvt;
        int r0 = (tl >> 4) * 32, c0 = (tl & 15) * 32;
        int tx = threadIdx.x & 31, ty = threadIdx.x >> 5;
        #pragma unroll
        for (int i = ty; i < 32; i += 8)
            tile[i][tx] = in[(size_t)(r0 + i) * DIM + c0 + tx];
        __syncthreads();
        #pragma unroll
        for (int i = ty; i < 32; i += 8)
            out[(size_t)(c0 + i) * DIM + r0 + tx] = __float2half_rn(tile[tx][i]);
    } else {
        // bias pack
        for (int t = threadIdx.x; t < DIM; t += 256) {
            g_bqk[t] = bq[t];
            g_bqk[DIM + t] = bk[t];
        }
    }
}

// ---------------- column sums combine -> 1/colsum ----------------
__global__ void __launch_bounds__(256) colstats2_kernel() {
    int j = blockIdx.x * 256 + threadIdx.x;
    int z = blockIdx.y;
    float s = 0.0f;
    #pragma unroll
    for (int c = 0; c < NCHUNK; c++)
        s += g_ps[((size_t)z * NCHUNK + c) * SEQ + j];
    g_csi[(size_t)z * SEQ + j] = 1.0f / s;
}

// ---------------- rowsum: rinv[i] = 1 / sum_j E[i,j]*csi[j] (read-only over E) ----
__global__ void __launch_bounds__(256) rowsum_kernel() {
    int i = blockIdx.x;
    int z = blockIdx.y;
    int t = threadIdx.x;
    const __half* row = g_e + ((size_t)z * SEQ + i) * SEQ;
    const float* ci = g_csi + (size_t)z * SEQ;
    float acc = 0.0f;
    #pragma unroll
    for (int j2 = t; j2 < SEQ / 2; j2 += 256) {
        int j = j2 * 2;
        __half2 e2 = *(const __half2*)(row + j);
        float2 c2 = *(const float2*)(ci + j);
        acc += __half2float(__low2half(e2))  * c2.x
             + __half2float(__high2half(e2)) * c2.y;
    }
    __shared__ float sh[8];
    #pragma unroll
    for (int o = 16; o > 0; o >>= 1)
        acc += __shfl_down_sync(0xffffffffu, acc, o);
    if ((t & 31) == 0) sh[t >> 5] = acc;
    __syncthreads();
    if (t == 0) {
        float s = 0.0f;
        #pragma unroll
        for (int w = 0; w < 8; w++) s += sh[w];
        g_rinv[(size_t)z * SEQ + i] = 1.0f / s;
    }
}

// ---------------- launch ----------------
extern "C" void kernel_launch(void* const* d_in, const int* in_sizes, int n_in,
                              void* d_out, int out_size) {
    const float* inputs  = (const float*)d_in[0];
    const float* context = (const float*)d_in[1];
    const float* gin  = (const float*)d_in[2];
    const float* bin  = (const float*)d_in[3];
    const float* gctx = (const float*)d_in[4];
    const float* bctx = (const float*)d_in[5];
    const float* Wq = (const float*)d_in[6];
    const float* bq = (const float*)d_in[7];
    const float* Wk = (const float*)d_in[8];
    const float* bk = (const float*)d_in[9];
    const float* Wv = (const float*)d_in[10];
    const float* bv = (const float*)d_in[11];
    float* out = (float*)d_out;

    __half *xc, *wqk, *wvt, *qk, *vt, *e;
    float *rinv, *bqk;
    cudaGetSymbolAddress((void**)&xc,   g_xc);
    cudaGetSymbolAddress((void**)&wqk,  g_wqk);
    cudaGetSymbolAddress((void**)&wvt,  g_wvt);
    cudaGetSymbolAddress((void**)&qk,   g_qk);
    cudaGetSymbolAddress((void**)&vt,   g_vt);
    cudaGetSymbolAddress((void**)&e,    g_e);
    cudaGetSymbolAddress((void**)&rinv, g_rinv);
    cudaGetSymbolAddress((void**)&bqk,  g_bqk);

    cudaFuncSetAttribute(gemm_h<0>, cudaFuncAttributeMaxDynamicSharedMemorySize, GEMM_DSMEM);
    cudaFuncSetAttribute(gemm_h<5>, cudaFuncAttributeMaxDynamicSharedMemorySize, GEMM_DSMEM);
    cudaFuncSetAttribute(gemm_h<6>, cudaFuncAttributeMaxDynamicSharedMemorySize, GEMM_DSMEM);
    cudaFuncSetAttribute(gemm_h<7>, cudaFuncAttributeMaxDynamicSharedMemorySize, GEMM_DSMEM);

    // one-time stream/event creation (host-side resources only; no device memory)
    static cudaStream_t s2 = nullptr;
    static cudaEvent_t evFork = nullptr, evJoin = nullptr;
    if (!s2) {
        cudaStreamCreateWithFlags(&s2, cudaStreamNonBlocking);
        cudaEventCreateWithFlags(&evFork, cudaEventDisableTiming);
        cudaEventCreateWithFlags(&evJoin, cudaEventDisableTiming);
    }

    // unified prep: LN + weight transposes + bias pack
    prep_kernel<<<LN_BLOCKS + TS_BLOCKS + 1, 256>>>(
        inputs, context, gin, bin, gctx, bctx, Wq, Wk, Wv, bq, bk);

    // q & k in one batched GEMM: z=0 -> q(xn,Wq,bq), z=1 -> k(cn,Wk,bk)
    {
        dim3 grid(DIM / 128, NR / 256, 2);
        gemm_h<5><<<grid, 256, GEMM_DSMEM>>>(xc, wqk, NR, DIM, DIM,
                                             (size_t)NR * DIM, (size_t)DIM * DIM,
                                             (size_t)NR * DIM,
                                             1.0f, bqk, DIM, nullptr, nullptr,
                                             nullptr, 0, nullptr, qk);
    }

    // E = exp(scale * q @ k^T) fp16 + fused column sums -> g_ps
    {
        float scale = 1.0f / sqrtf((float)DIM);
        dim3 grid(SEQ / 128, SEQ / 256, BATCH);
        gemm_h<6><<<grid, 256, GEMM_DSMEM>>>(qk, qk + (size_t)NR * DIM, SEQ, SEQ, DIM,
                                             (size_t)SEQ * DIM, (size_t)SEQ * DIM,
                                             (size_t)SEQ * SEQ, scale,
                                             nullptr, 0, nullptr, nullptr,
                                             nullptr, 0, nullptr, e);
    }

    // fork immediately after E: vt' (inline csi from g_ps) on s2,
    // colstats2 + rowsum on main stream
    cudaEventRecord(evFork, 0);
    cudaStreamWaitEvent(s2, evFork, 0);
    {
        dim3 grid(SEQ / 128, DIM / 256, BATCH);
        gemm_h<7><<<grid, 256, GEMM_DSMEM, s2>>>(wvt, xc + (size_t)NR * DIM, DIM, SEQ, DIM,
                                                 0, (size_t)SEQ * DIM, (size_t)DIM * SEQ,
                                                 1.0f, nullptr, 0, bv, nullptr,
                                                 nullptr, 0, nullptr, vt);
    }
    cudaEventRecord(evJoin, s2);

    // main stream: csi = 1/colsum ; rinv[i] = 1 / sum_j E[i,j]*csi[j]
    colstats2_kernel<<<dim3(SEQ / 256, BATCH), 256>>>();
    rowsum_kernel<<<dim3(SEQ, BATCH), 256>>>();

    cudaStreamWaitEvent(0, evJoin, 0);

    // out = rinv[i] * (E @ vt'^T) (M=2048, N=512, Kc=2048, batched)
    {
        dim3 grid(DIM / 128, SEQ / 256, BATCH);
        gemm_h<0><<<grid, 256, GEMM_DSMEM>>>(e, vt, SEQ, DIM, SEQ,
                                             (size_t)SEQ * SEQ, (size_t)DIM * SEQ,
                                             (size_t)SEQ * DIM, 1.0f,
                                             nullptr, 0, nullptr, rinv,
                                             nullptr, 0, out, nullptr);
    }
}

// round 17
// speedup vs baseline: 1.0593x; 1.0018x over previous
#include <cuda_runtime.h>
#include <cuda_fp16.h>
#include <math.h>
#include <stdint.h>

#define BATCH 8
#define SEQ   2048
#define DIM   512
#define NCHUNK 8          // 256-row chunks of SEQ (dots M-tiles)
#define NR    (BATCH * SEQ)
#define LN_BLOCKS (NR)            // 2*NR rows, 2 rows per block
#define TS_BLOCKS 256             // Wv transpose tiles only

static const float LN_EPS_F = 1e-5f;

// ---------------- scratch (static device globals; no allocation) ----------------
__device__ __align__(256) __half g_xc [(size_t)2 * NR * DIM];   // [xn | cn]
__device__ __align__(256) __half g_BH [(size_t)DIM * DIM];      // BH[b,a] = sum_o Wk[b,o]Wq[a,o]
__device__ __align__(256) __half g_wvt[(size_t)DIM * DIM];
__device__ __align__(256) __half g_tmp[(size_t)NR * DIM];       // tmp = xn @ H
__device__ __align__(256) __half g_vt [(size_t)BATCH * DIM * SEQ];  // vt' = vt * csi
__device__ __align__(256) __half g_e  [(size_t)BATCH * SEQ * SEQ];  // E = exp(dots*scale)
__device__ float g_ps  [BATCH * NCHUNK * SEQ];
__device__ float g_csi [BATCH * SEQ];
__device__ float g_rinv[BATCH * SEQ];
__device__ float g_bvec[1025];    // [0..511] Wq@bk, [512..1023] Wk@bq, [1024] bq.bk
__device__ float g_r   [NR];      // r[i] = xn[i].wqbk + bq.bk
__device__ float g_c   [NR];      // c[j] = cn[j].wkbq

// ---------------- PTX helpers (baseline compute_103-safe) ----------------
__device__ __forceinline__ uint32_t smem_u32(const void* p) {
    uint32_t a;
    asm("{ .reg .u64 t; cvta.to.shared.u64 t, %1; cvt.u32.u64 %0, t; }" : "=r"(a) : "l"(p));
    return a;
}
__device__ __forceinline__ void cp_async16(uint32_t d, const void* g) {
    asm volatile("cp.async.cg.shared.global [%0], [%1], 16;" :: "r"(d), "l"(g));
}
__device__ __forceinline__ void cp_commit() {
    asm volatile("cp.async.commit_group;" ::: "memory");
}
template <int N>
__device__ __forceinline__ void cp_wait() {
    asm volatile("cp.async.wait_group %0;" :: "n"(N) : "memory");
}
__device__ __forceinline__ void ldsm4(uint32_t& r0, uint32_t& r1, uint32_t& r2, uint32_t& r3,
                                      uint32_t addr) {
    asm volatile("ldmatrix.sync.aligned.m8n8.x4.shared.b16 {%0,%1,%2,%3}, [%4];"
                 : "=r"(r0), "=r"(r1), "=r"(r2), "=r"(r3) : "r"(addr));
}
__device__ __forceinline__ void mma16816(float* c, const uint32_t* a, uint32_t b0, uint32_t b1) {
    asm volatile(
        "mma.sync.aligned.m16n8k16.row.col.f32.f16.f16.f32 "
        "{%0,%1,%2,%3}, {%4,%5,%6,%7}, {%8,%9}, {%0,%1,%2,%3};"
        : "+f"(c[0]), "+f"(c[1]), "+f"(c[2]), "+f"(c[3])
        : "r"(a[0]), "r"(a[1]), "r"(a[2]), "r"(a[3]), "r"(b0), "r"(b1));
}

// ---------------- HMMA plain-fp16 GEMM, CTA tile 256x128, warp tile 64x64 ----
// Compile-time PATTERN specialization:
// 0: outf = (acc*alpha + bias_row) * rowscale[z*M+row]
// 5: outh = fp16(acc*alpha + bias_row)
// 6: outh = fp16(exp((acc + g_r[z*SEQ+row] + g_c[z*SEQ+col]) * alpha));
//    fused column sums -> g_ps (per 256-row chunk)
// 7: like 5 but colscale computed inline from g_ps
#define BK 32
#define STAGES 5
#define A_STAGE (256 * 80)
#define B_STAGE (128 * 80)
#define STAGE_BYTES (A_STAGE + B_STAGE)
#define GEMM_DSMEM (STAGES * STAGE_BYTES)

template <int PATTERN>
__global__ void __launch_bounds__(256, 1) gemm_h(
    const __half* __restrict__ A, const __half* __restrict__ B,
    int M, int N, int Kc,
    size_t sA, size_t sB, size_t sC,
    float alpha,
    const float* __restrict__ bias_row,
    const float* __restrict__ rowscale,
    float* __restrict__ outf, __half* __restrict__ outh)
{
    extern __shared__ char dyn[];
    __shared__ float csbuf[128];
    uint32_t dynb = smem_u32(dyn);

    int z = blockIdx.z;
    const __half* Ab = A + (size_t)z * sA + (size_t)(blockIdx.y * 256) * Kc;
    const __half* Bb = B + (size_t)z * sB + (size_t)(blockIdx.x * 128) * Kc;
    int bm = blockIdx.y * 256;
    int bn = blockIdx.x * 128;

    int t = threadIdx.x;
    int wid = t >> 5, lane = t & 31;
    int wm = wid & 3;        // 4 warps over M (64 rows each)
    int wn = wid >> 2;       // 2 warps over N (64 cols each)

    // PATTERN 7 prologue: inline csi for this CTA's 128 columns (of N=SEQ)
    if (PATTERN == 7 && t < 128) {
        int col = bn + t;
        float s = 0.0f;
        #pragma unroll
        for (int c = 0; c < NCHUNK; c++)
            s += g_ps[((size_t)z * NCHUNK + c) * SEQ + col];
        csbuf[t] = 1.0f / s;
    }

    float acc[4][8][4];
    #pragma unroll
    for (int i = 0; i < 4; i++)
        #pragma unroll
        for (int j = 0; j < 8; j++)
            #pragma unroll
            for (int r = 0; r < 4; r++) acc[i][j][r] = 0.0f;

    int nkb = Kc / BK;

    auto issue = [&](int kb) {
        int slot = kb % STAGES;
        uint32_t sa = dynb + slot * STAGE_BYTES;
        uint32_t sb = sa + A_STAGE;
        int kh = kb * BK;
        #pragma unroll
        for (int i = 0; i < 4; i++) {           // A: 256 rows x 32 k
            int idx = t + 256 * i;
            int row = idx >> 2, c = idx & 3;
            cp_async16(sa + row * 80 + c * 16, Ab + (size_t)row * Kc + kh + c * 8);
        }
        #pragma unroll
        for (int i = 0; i < 2; i++) {           // B: 128 rows x 32 k
            int idx = t + 256 * i;
            int row = idx >> 2, c = idx & 3;
            cp_async16(sb + row * 80 + c * 16, Bb + (size_t)row * Kc + kh + c * 8);
        }
    };

    issue(0); cp_commit();
    issue(1); cp_commit();
    issue(2); cp_commit();
    issue(3); cp_commit();

    uint32_t a_lane = (uint32_t)((wm * 64 + (lane & 15)) * 80 + ((lane >> 4) * 8) * 2);
    uint32_t b_lane = (uint32_t)(A_STAGE +
                       (wn * 64 + (lane & 7) + (lane >> 4) * 8) * 80 +
                       (((lane >> 3) & 1) * 8) * 2);

    cp_wait<2>();          // slots 0 and 1 ready
    __syncthreads();

    uint32_t af[2][4][4];  // A fragments, double buffered (4 x m16)
    uint32_t bf[2][4][4];  // B fragments, double buffered (4 x n16)

    {
        uint32_t s0 = dynb;
        #pragma unroll
        for (int mi = 0; mi < 4; mi++)
            ldsm4(af[0][mi][0], af[0][mi][1], af[0][mi][2], af[0][mi][3],
                  s0 + a_lane + mi * (16 * 80));
        #pragma unroll
        for (int g = 0; g < 4; g++)
            ldsm4(bf[0][g][0], bf[0][g][1], bf[0][g][2], bf[0][g][3],
                  s0 + b_lane + g * (16 * 80));
    }

    int p = 0;
    for (int kb = 0; kb < nkb; kb++) {
        if (kb + 4 < nkb) issue(kb + 4);
        cp_commit();
        uint32_t scur = dynb + (kb % STAGES) * STAGE_BYTES;
        uint32_t snxt = dynb + ((kb + 1) % STAGES) * STAGE_BYTES;

        // ---- ks = 0: prefetch (kb, ks1) into p^1, mma on p ----
        #pragma unroll
        for (int mi = 0; mi < 4; mi++)
            ldsm4(af[p^1][mi][0], af[p^1][mi][1], af[p^1][mi][2], af[p^1][mi][3],
                  scur + a_lane + mi * (16 * 80) + 32);
        #pragma unroll
        for (int g = 0; g < 4; g++)
            ldsm4(bf[p^1][g][0], bf[p^1][g][1], bf[p^1][g][2], bf[p^1][g][3],
                  scur + b_lane + g * (16 * 80) + 32);
        #pragma unroll
        for (int mi = 0; mi < 4; mi++)
            #pragma unroll
            for (int ni = 0; ni < 8; ni++)
                mma16816(acc[mi][ni], af[p][mi],
                         bf[p][ni >> 1][(ni & 1) * 2], bf[p][ni >> 1][(ni & 1) * 2 + 1]);
        p ^= 1;

        // ---- ks = 1: prefetch (kb+1, ks0) into p^1, mma on p ----
        if (kb + 1 < nkb) {
            #pragma unroll
            for (int mi = 0; mi < 4; mi++)
                ldsm4(af[p^1][mi][0], af[p^1][mi][1], af[p^1][mi][2], af[p^1][mi][3],
                      snxt + a_lane + mi * (16 * 80));
            #pragma unroll
            for (int g = 0; g < 4; g++)
                ldsm4(bf[p^1][g][0], bf[p^1][g][1], bf[p^1][g][2], bf[p^1][g][3],
                      snxt + b_lane + g * (16 * 80));
        }
        #pragma unroll
        for (int mi = 0; mi < 4; mi++)
            #pragma unroll
            for (int ni = 0; ni < 8; ni++)
                mma16816(acc[mi][ni], af[p][mi],
                         bf[p][ni >> 1][(ni & 1) * 2], bf[p][ni >> 1][(ni & 1) * 2 + 1]);
        p ^= 1;

        cp_wait<2>();
        __syncthreads();
    }

    // ---------------- store epilogue ----------------
    int r_lane = lane >> 2;
    int c_lane = (lane & 3) * 2;

    if (PATTERN == 6) {
        float csum[8][2];
        #pragma unroll
        for (int ni = 0; ni < 8; ni++) { csum[ni][0] = 0.0f; csum[ni][1] = 0.0f; }

        #pragma unroll
        for (int mi = 0; mi < 4; mi++) {
            #pragma unroll
            for (int ni = 0; ni < 8; ni++) {
                int row = bm + wm * 64 + mi * 16 + r_lane;
                int col = bn + wn * 64 + ni * 8 + c_lane;
                float* a4 = acc[mi][ni];
                float cc0 = g_c[(size_t)z * SEQ + col];
                float cc1 = g_c[(size_t)z * SEQ + col + 1];
                #pragma unroll
                for (int h = 0; h < 2; h++) {
                    int rr = row + h * 8;
                    float rb = g_r[(size_t)z * SEQ + rr];
                    float e0 = __expf((a4[h * 2 + 0] + rb + cc0) * alpha);
                    float e1 = __expf((a4[h * 2 + 1] + rb + cc1) * alpha);
                    csum[ni][0] += e0;
                    csum[ni][1] += e1;
                    __half2 hh = __halves2half2(__float2half_rn(e0), __float2half_rn(e1));
                    *(__half2*)(outh + (size_t)z * sC + (size_t)rr * N + col) = hh;
                }
            }
        }
        // reduce over the 8 lane-rows (lane bits 2..4)
        #pragma unroll
        for (int o = 4; o < 32; o <<= 1)
            #pragma unroll
            for (int ni = 0; ni < 8; ni++) {
                csum[ni][0] += __shfl_xor_sync(0xffffffffu, csum[ni][0], o);
                csum[ni][1] += __shfl_xor_sync(0xffffffffu, csum[ni][1], o);
            }
        cp_wait<0>();
        __syncthreads();
        float* ssm = (float*)dyn;            // [4][128]
        if ((lane >> 2) == 0) {
            #pragma unroll
            for (int ni = 0; ni < 8; ni++) {
                int col = wn * 64 + ni * 8 + (lane & 3) * 2;
                ssm[wm * 128 + col]     = csum[ni][0];
                ssm[wm * 128 + col + 1] = csum[ni][1];
            }
        }
        __syncthreads();
        if (t < 128) {
            float s = ssm[t] + ssm[128 + t] + ssm[256 + t] + ssm[384 + t];
            g_ps[((size_t)z * NCHUNK + blockIdx.y) * SEQ + bn + t] = s;
        }
        return;
    }

    #pragma unroll
    for (int mi = 0; mi < 4; mi++) {
        #pragma unroll
        for (int ni = 0; ni < 8; ni++) {
            int row = bm + wm * 64 + mi * 16 + r_lane;
            int col = bn + wn * 64 + ni * 8 + c_lane;
            float* a4 = acc[mi][ni];
            float cs0 = 1.0f, cs1 = 1.0f;
            if (PATTERN == 7) {
                cs0 = csbuf[col - bn];
                cs1 = csbuf[col - bn + 1];
            }
            #pragma unroll
            for (int h = 0; h < 2; h++) {
                int rr = row + h * 8;
                float br = bias_row ? bias_row[rr] : 0.0f;
                float v0 = (a4[h * 2 + 0] * alpha + br) * cs0;
                float v1 = (a4[h * 2 + 1] * alpha + br) * cs1;
                if (PATTERN == 0) {
                    float rs = rowscale ? rowscale[(size_t)z * M + rr] : 1.0f;
                    float2 o = make_float2(v0 * rs, v1 * rs);
                    *(float2*)(outf + (size_t)z * sC + (size_t)rr * N + col) = o;
                } else {  // 5 / 7: fp16
                    __half2 hh = __halves2half2(__float2half_rn(v0), __float2half_rn(v1));
                    *(__half2*)(outh + (size_t)z * sC + (size_t)rr * N + col) = hh;
                }
            }
        }
    }
}

// ---------------- bvec: wqbk = Wq@bk, wkbq = Wk@bq, bq.bk ----------------
__global__ void __launch_bounds__(128) bvec_kernel(const float* __restrict__ Wq,
                                                   const float* __restrict__ Wk,
                                                   const float* __restrict__ bq,
                                                   const float* __restrict__ bk) {
    __shared__ float sh[4];
    int blk = blockIdx.x;
    int t = threadIdx.x;
    float acc;
    if (blk < 1024) {
        int r = blk & 511;
        const float* W  = (blk < 512) ? Wq : Wk;
        const float* bv = (blk < 512) ? bk : bq;
        float4 w  = ((const float4*)(W + (size_t)r * DIM))[t];
        float4 b4 = ((const float4*)bv)[t];
        acc = w.x*b4.x + w.y*b4.y + w.z*b4.z + w.w*b4.w;
    } else {
        float4 a4 = ((const float4*)bq)[t];
        float4 b4 = ((const float4*)bk)[t];
        acc = a4.x*b4.x + a4.y*b4.y + a4.z*b4.z + a4.w*b4.w;
    }
    #pragma unroll
    for (int o = 16; o > 0; o >>= 1)
        acc += __shfl_down_sync(0xffffffffu, acc, o);
    if ((t & 31) == 0) sh[t >> 5] = acc;
    __syncthreads();
    if (t == 0)
        g_bvec[blk] = sh[0] + sh[1] + sh[2] + sh[3];
}

// ---------------- gmat: BH[b,a] = sum_o Wk[b,o]*Wq[a,o] (fp32 in, fp16 out) ----
__global__ void __launch_bounds__(256) gmat_kernel(const float* __restrict__ Wq,
                                                   const float* __restrict__ Wk) {
    __shared__ float sk[64][33], sq[64][33];
    int b0 = blockIdx.y * 64, a0 = blockIdx.x * 64;
    int tid = threadIdx.x;
    int ty = tid >> 4, tx = tid & 15;
    float acc[4][4];
    #pragma unroll
    for (int i = 0; i < 4; i++)
        #pragma unroll
        for (int j = 0; j < 4; j++) acc[i][j] = 0.0f;
    for (int o0 = 0; o0 < DIM; o0 += 32) {
        #pragma unroll
        for (int i = 0; i < 8; i++) {
            int idx = tid + 256 * i;
            int r = idx >> 5, c = idx & 31;
            sk[r][c] = Wk[(size_t)(b0 + r) * DIM + o0 + c];
            sq[r][c] = Wq[(size_t)(a0 + r) * DIM + o0 + c];
        }
        __syncthreads();
        #pragma unroll
        for (int o = 0; o < 32; o++) {
            float kk[4], qq[4];
            #pragma unroll
            for (int i = 0; i < 4; i++) { kk[i] = sk[ty*4+i][o]; qq[i] = sq[tx*4+i][o]; }
            #pragma unroll
            for (int i = 0; i < 4; i++)
                #pragma unroll
                for (int j = 0; j < 4; j++)
                    acc[i][j] = fmaf(kk[i], qq[j], acc[i][j]);
        }
        __syncthreads();
    }
    #pragma unroll
    for (int i = 0; i < 4; i++)
        #pragma unroll
        for (int j = 0; j < 4; j++)
            g_BH[(size_t)(b0 + ty*4 + i) * DIM + a0 + tx*4 + j] = __float2half_rn(acc[i][j]);
}

// ---------------- unified prep: LN (2 rows/block, + r/c dots) + Wv transpose ----
__global__ void __launch_bounds__(256) prep_kernel(
    const float* __restrict__ xin, const float* __restrict__ cin,
    const float* __restrict__ gx, const float* __restrict__ bx,
    const float* __restrict__ gc, const float* __restrict__ bc,
    const float* __restrict__ Wv)
{
    int blk = blockIdx.x;
    if (blk < LN_BLOCKS) {
        __shared__ float sh[2][8];
        __shared__ float sh2[2][4];
        int half = threadIdx.x >> 7;      // 0 or 1
        int t = threadIdx.x & 127;
        int row = blk * 2 + half;         // 0 .. 2*NR-1
        const float* x;
        const float* g;
        const float* b;
        __half* y;
        if (row < NR) {
            x = xin + (size_t)row * DIM; g = gx; b = bx;
            y = g_xc + (size_t)row * DIM;
        } else {
            int r2 = row - NR;
            x = cin + (size_t)r2 * DIM; g = gc; b = bc;
            y = g_xc + (size_t)NR * DIM + (size_t)r2 * DIM;
        }
        float4 v = ((const float4*)x)[t];
        float s  = v.x + v.y + v.z + v.w;
        float ss = v.x*v.x + v.y*v.y + v.z*v.z + v.w*v.w;
        #pragma unroll
        for (int o = 16; o > 0; o >>= 1) {
            s  += __shfl_down_sync(0xffffffffu, s, o);
            ss += __shfl_down_sync(0xffffffffu, ss, o);
        }
        if ((t & 31) == 0) { sh[half][t >> 5] = s; sh[half][4 + (t >> 5)] = ss; }
        __syncthreads();
        float fs  = sh[half][0] + sh[half][1] + sh[half][2] + sh[half][3];
        float fss = sh[half][4] + sh[half][5] + sh[half][6] + sh[half][7];
        float mu  = fs * (1.0f / DIM);
        float var = fss * (1.0f / DIM) - mu * mu;
        float rstd = rsqrtf(var + LN_EPS_F);
        float4 gv = ((const float4*)g)[t];
        float4 bv = ((const float4*)b)[t];
        float o0 = (v.x - mu) * rstd * gv.x + bv.x;
        float o1 = (v.y - mu) * rstd * gv.y + bv.y;
        float o2 = (v.z - mu) * rstd * gv.z + bv.z;
        float o3 = (v.w - mu) * rstd * gv.w + bv.w;
        ((__half2*)(y + t * 4))[0] = __halves2half2(__float2half_rn(o0), __float2half_rn(o1));
        ((__half2*)(y + t * 4))[1] = __halves2half2(__float2half_rn(o2), __float2half_rn(o3));

        // r/c cross-bias dots: r[i] = xn[i].wqbk + bq.bk ; c[j] = cn[j].wkbq
        const float* wv = (row < NR) ? g_bvec : (g_bvec + DIM);
        float4 w4 = ((const float4*)wv)[t];
        float rsum = o0 * w4.x + o1 * w4.y + o2 * w4.z + o3 * w4.w;
        #pragma unroll
        for (int o = 16; o > 0; o >>= 1)
            rsum += __shfl_down_sync(0xffffffffu, rsum, o);
        if ((t & 31) == 0) sh2[half][t >> 5] = rsum;
        __syncthreads();
        if (t == 0) {
            float rs = sh2[half][0] + sh2[half][1] + sh2[half][2] + sh2[half][3];
            if (row < NR) g_r[row] = rs + g_bvec[1024];
            else          g_c[row - NR] = rs;
        }
    } else {
        // Wv transpose tiles
        __shared__ float tile[32][33];
        int tl = blk - LN_BLOCKS;    // 0..255
        int r0 = (tl >> 4) * 32, c0 = (tl & 15) * 32;
        int tx = threadIdx.x & 31, ty = threadIdx.x >> 5;
        #pragma unroll
        for (int i = ty; i < 32; i += 8)
            tile[i][tx] = Wv[(size_t)(r0 + i) * DIM + c0 + tx];
        __syncthreads();
        #pragma unroll
        for (int i = ty; i < 32; i += 8)
            g_wvt[(size_t)(c0 + i) * DIM + r0 + tx] = __float2half_rn(tile[tx][i]);
    }
}

// ---------------- column sums combine -> 1/colsum ----------------
__global__ void __launch_bounds__(256) colstats2_kernel() {
    int j = blockIdx.x * 256 + threadIdx.x;
    int z = blockIdx.y;
    float s = 0.0f;
    #pragma unroll
    for (int c = 0; c < NCHUNK; c++)
        s += g_ps[((size_t)z * NCHUNK + c) * SEQ + j];
    g_csi[(size_t)z * SEQ + j] = 1.0f / s;
}

// ---------------- rowsum: rinv[i] = 1 / sum_j E[i,j]*csi[j] ----------------
__global__ void __launch_bounds__(256) rowsum_kernel() {
    int i = blockIdx.x;
    int z = blockIdx.y;
    int t = threadIdx.x;
    const __half* row = g_e + ((size_t)z * SEQ + i) * SEQ;
    const float* ci = g_csi + (size_t)z * SEQ;
    float acc = 0.0f;
    #pragma unroll
    for (int j2 = t; j2 < SEQ / 2; j2 += 256) {
        int j = j2 * 2;
        __half2 e2 = *(const __half2*)(row + j);
        float2 c2 = *(const float2*)(ci + j);
        acc += __half2float(__low2half(e2))  * c2.x
             + __half2float(__high2half(e2)) * c2.y;
    }
    __shared__ float sh[8];
    #pragma unroll
    for (int o = 16; o > 0; o >>= 1)
        acc += __shfl_down_sync(0xffffffffu, acc, o);
    if ((t & 31) == 0) sh[t >> 5] = acc;
    __syncthreads();
    if (t == 0) {
        float s = 0.0f;
        #pragma unroll
        for (int w = 0; w < 8; w++) s += sh[w];
        g_rinv[(size_t)z * SEQ + i] = 1.0f / s;
    }
}

// ---------------- launch ----------------
extern "C" void kernel_launch(void* const* d_in, const int* in_sizes, int n_in,
                              void* d_out, int out_size) {
    const float* inputs  = (const float*)d_in[0];
    const float* context = (const float*)d_in[1];
    const float* gin  = (const float*)d_in[2];
    const float* bin  = (const float*)d_in[3];
    const float* gctx = (const float*)d_in[4];
    const float* bctx = (const float*)d_in[5];
    const float* Wq = (const float*)d_in[6];
    const float* bq = (const float*)d_in[7];
    const float* Wk = (const float*)d_in[8];
    const float* bk = (const float*)d_in[9];
    const float* Wv = (const float*)d_in[10];
    const float* bv = (const float*)d_in[11];
    float* out = (float*)d_out;

    __half *xc, *BH, *wvt, *tmp, *vt, *e;
    float *rinv;
    cudaGetSymbolAddress((void**)&xc,   g_xc);
    cudaGetSymbolAddress((void**)&BH,   g_BH);
    cudaGetSymbolAddress((void**)&wvt,  g_wvt);
    cudaGetSymbolAddress((void**)&tmp,  g_tmp);
    cudaGetSymbolAddress((void**)&vt,   g_vt);
    cudaGetSymbolAddress((void**)&e,    g_e);
    cudaGetSymbolAddress((void**)&rinv, g_rinv);

    cudaFuncSetAttribute(gemm_h<0>, cudaFuncAttributeMaxDynamicSharedMemorySize, GEMM_DSMEM);
    cudaFuncSetAttribute(gemm_h<5>, cudaFuncAttributeMaxDynamicSharedMemorySize, GEMM_DSMEM);
    cudaFuncSetAttribute(gemm_h<6>, cudaFuncAttributeMaxDynamicSharedMemorySize, GEMM_DSMEM);
    cudaFuncSetAttribute(gemm_h<7>, cudaFuncAttributeMaxDynamicSharedMemorySize, GEMM_DSMEM);

    // one-time stream/event creation (host-side resources only; no device memory)
    static cudaStream_t s2 = nullptr;
    static cudaEvent_t evF0 = nullptr, evJ0 = nullptr, evFork = nullptr, evJoin = nullptr;
    if (!s2) {
        cudaStreamCreateWithFlags(&s2, cudaStreamNonBlocking);
        cudaEventCreateWithFlags(&evF0,   cudaEventDisableTiming);
        cudaEventCreateWithFlags(&evJ0,   cudaEventDisableTiming);
        cudaEventCreateWithFlags(&evFork, cudaEventDisableTiming);
        cudaEventCreateWithFlags(&evJoin, cudaEventDisableTiming);
    }

    // fork 0: H = Wq @ Wk^T on s2 (depends only on raw inputs), hidden under prep
    cudaEventRecord(evF0, 0);
    cudaStreamWaitEvent(s2, evF0, 0);
    gmat_kernel<<<dim3(8, 8), 256, 0, s2>>>(Wq, Wk);
    cudaEventRecord(evJ0, s2);

    // main: cross-bias vectors, then LN (+ r/c dots) + Wv transpose
    bvec_kernel<<<1025, 128>>>(Wq, Wk, bq, bk);
    prep_kernel<<<LN_BLOCKS + TS_BLOCKS, 256>>>(
        inputs, context, gin, bin, gctx, bctx, Wv);

    // tmp = xn @ H (M=NR, N=512, Kc=512) — needs gmat
    cudaStreamWaitEvent(0, evJ0, 0);
    {
        dim3 grid(DIM / 128, NR / 256, 1);
        gemm_h<5><<<grid, 256, GEMM_DSMEM>>>(xc, BH, NR, DIM, DIM,
                                             0, 0, 0,
                                             1.0f, nullptr, nullptr,
                                             nullptr, tmp);
    }

    // E = exp(scale * (tmp @ cn^T + r + c)) fp16 + fused column sums -> g_ps
    {
        float scale = 1.0f / sqrtf((float)DIM);
        dim3 grid(SEQ / 128, SEQ / 256, BATCH);
        gemm_h<6><<<grid, 256, GEMM_DSMEM>>>(tmp, xc + (size_t)NR * DIM, SEQ, SEQ, DIM,
                                             (size_t)SEQ * DIM, (size_t)SEQ * DIM,
                                             (size_t)SEQ * SEQ, scale,
                                             nullptr, nullptr,
                                             nullptr, e);
    }

    // fork: vt' (inline csi from g_ps) on s2; colstats2 + rowsum on main
    cudaEventRecord(evFork, 0);
    cudaStreamWaitEvent(s2, evFork, 0);
    {
        dim3 grid(SEQ / 128, DIM / 256, BATCH);
        gemm_h<7><<<grid, 256, GEMM_DSMEM, s2>>>(wvt, xc + (size_t)NR * DIM, DIM, SEQ, DIM,
                                                 0, (size_t)SEQ * DIM, (size_t)DIM * SEQ,
                                                 1.0f, bv, nullptr,
                                                 nullptr, vt);
    }
    cudaEventRecord(evJoin, s2);

    colstats2_kernel<<<dim3(SEQ / 256, BATCH), 256>>>();
    rowsum_kernel<<<dim3(SEQ, BATCH), 256>>>();

    cudaStreamWaitEvent(0, evJoin, 0);

    // out = rinv[i] * (E @ vt'^T) (M=2048, N=512, Kc=2048, batched)
    {
        dim3 grid(DIM / 128, SEQ / 256, BATCH);
        gemm_h<0><<<grid, 256, GEMM_DSMEM>>>(e, vt, SEQ, DIM, SEQ,
                                             (size_t)SEQ * SEQ, (size_t)DIM * SEQ,
                                             (size_t)SEQ * DIM, 1.0f,
                                             nullptr, rinv,
                                             out, nullptr);
    }
}